// round 13
// baseline (speedup 1.0000x reference)
#include <cuda_runtime.h>
#include <cuda_bf16.h>
#include <math.h>
#include <stdint.h>

#define BB 32
#define SS 512
#define DD 768
#define HH 12
#define EE 64

#define M_TOT (BB*SS)        // 16384
#define N_QKV (3*DD)         // 2304
#define NKC   (DD/64)        // 12 base-k chunks of 64 (bf16 GEMM)
#define NKCI  (DD/128)       // 6 k-chunks of 128 (int8 GEMM)

// bf16 GEMM tiling: 256x128 CTA tile, 8 warps (4x2), warp tile 64x64, 2-stage
#define S_AHI 0
#define S_ALO 32768
#define S_BHI 65536
#define S_BLO 81920
#define STG   98304          // 96KB per stage
#define G_SMEM (2*STG)       // 192KB

// int8 proj GEMM smem per stage: A1 16K | A2 16K | B1 8K | B2 8K = 48KB, 2 stages
#define I_A1 0
#define I_A2 16384
#define I_B1 32768
#define I_B2 40960
#define ISTG 49152
#define I_SMEM (2*ISTG)      // 96KB

// ---------------- device scratch ----------------
__device__ __nv_bfloat16 g_xhi[M_TOT*DD],  g_xlo[M_TOT*DD];    // x split
__device__ __nv_bfloat16 g_ashi[M_TOT*DD], g_aslo[M_TOT*DD];   // attn out split
__device__ __nv_bfloat16 g_wqhi[N_QKV*DD], g_wqlo[N_QKV*DD];   // qkv W^T split
__device__ __nv_bfloat16 g_qhi[BB*HH*SS*EE], g_qlo[BB*HH*SS*EE];
__device__ __nv_bfloat16 g_khi[BB*HH*SS*EE], g_klo[BB*HH*SS*EE];
__device__ __nv_bfloat16 g_vhi[BB*HH*SS*EE], g_vlo[BB*HH*SS*EE];
// int8 proj path
__device__ int8_t g_a1[M_TOT*DD], g_a2[M_TOT*DD];
__device__ float  g_sa[M_TOT];
__device__ int8_t g_wo1[DD*DD],   g_wo2[DD*DD];
__device__ float  g_swo[DD];

// ---------------- helpers ----------------
#define SW128(o) ((o) ^ (((o) >> 3) & 0x70))

__device__ __forceinline__ uint32_t smem_u32(const void* p) {
    return (uint32_t)__cvta_generic_to_shared(p);
}
__device__ __forceinline__ void cp16(uint32_t dst, const void* src) {
    asm volatile("cp.async.cg.shared.global [%0], [%1], 16;" :: "r"(dst), "l"(src) : "memory");
}
__device__ __forceinline__ void cp_commit() {
    asm volatile("cp.async.commit_group;" ::: "memory");
}
template <int N> __device__ __forceinline__ void cp_wait() {
    asm volatile("cp.async.wait_group %0;" :: "n"(N) : "memory");
}
__device__ __forceinline__ void ldsm4(uint32_t& a, uint32_t& b, uint32_t& c, uint32_t& d,
                                      uint32_t addr) {
    asm volatile("ldmatrix.sync.aligned.m8n8.x4.shared.b16 {%0,%1,%2,%3}, [%4];"
                 : "=r"(a), "=r"(b), "=r"(c), "=r"(d) : "r"(addr));
}
__device__ __forceinline__ void ldsm4t(uint32_t& a, uint32_t& b, uint32_t& c, uint32_t& d,
                                       uint32_t addr) {
    asm volatile("ldmatrix.sync.aligned.m8n8.x4.trans.shared.b16 {%0,%1,%2,%3}, [%4];"
                 : "=r"(a), "=r"(b), "=r"(c), "=r"(d) : "r"(addr));
}
__device__ __forceinline__ void mma16816(float& c0, float& c1, float& c2, float& c3,
                                         uint32_t a0, uint32_t a1, uint32_t a2, uint32_t a3,
                                         uint32_t b0, uint32_t b1) {
    asm volatile(
        "mma.sync.aligned.m16n8k16.row.col.f32.bf16.bf16.f32 "
        "{%0,%1,%2,%3}, {%4,%5,%6,%7}, {%8,%9}, {%0,%1,%2,%3};"
        : "+f"(c0), "+f"(c1), "+f"(c2), "+f"(c3)
        : "r"(a0), "r"(a1), "r"(a2), "r"(a3), "r"(b0), "r"(b1));
}
__device__ __forceinline__ void imma16832(int& c0, int& c1, int& c2, int& c3,
                                          uint32_t a0, uint32_t a1, uint32_t a2, uint32_t a3,
                                          uint32_t b0, uint32_t b1) {
    asm volatile(
        "mma.sync.aligned.m16n8k32.row.col.s32.s8.s8.s32 "
        "{%0,%1,%2,%3}, {%4,%5,%6,%7}, {%8,%9}, {%0,%1,%2,%3};"
        : "+r"(c0), "+r"(c1), "+r"(c2), "+r"(c3)
        : "r"(a0), "r"(a1), "r"(a2), "r"(a3), "r"(b0), "r"(b1));
}
__device__ __forceinline__ uint32_t pack_hi(float v0, float v1) {
    return __byte_perm(__float_as_uint(v0), __float_as_uint(v1), 0x7632);
}
__device__ __forceinline__ float trunc_bf(float v) {
    return __uint_as_float(__float_as_uint(v) & 0xffff0000u);
}
__device__ __forceinline__ uint32_t pack_rn(float l0, float l1) {
    uint32_t r;
    asm("cvt.rn.bf16x2.f32 %0, %1, %2;" : "=r"(r) : "f"(l1), "f"(l0));
    return r;
}

// ---------------------------------------------------------------------------
// prep kernels (round-7 verbatim): fp32 -> separate hi/lo bf16 arrays
// ---------------------------------------------------------------------------
__global__ void prep_x(const float* __restrict__ x) {
    int i = blockIdx.x * 256 + threadIdx.x;
    if (i >= M_TOT * DD) return;
    float v = x[i];
    __nv_bfloat16 h = __float2bfloat16(v);
    g_xhi[i] = h;
    g_xlo[i] = __float2bfloat16(v - __bfloat162float(h));
}
__global__ void prep_wqkv(const float* __restrict__ Wq, const float* __restrict__ Wk,
                          const float* __restrict__ Wv) {
    int i = blockIdx.x * 256 + threadIdx.x;
    if (i >= N_QKV * DD) return;
    int n = i / DD, k = i - (i / DD) * DD;
    int which = n / DD;
    int rem = n - which * DD;
    int h = rem >> 6, e = rem & 63;
    const float* W = (which == 0) ? Wq : (which == 1) ? Wk : Wv;
    float v = W[((size_t)h * DD + k) * EE + e];
    __nv_bfloat16 hv = __float2bfloat16(v);
    g_wqhi[i] = hv;
    g_wqlo[i] = __float2bfloat16(v - __bfloat162float(hv));
}

// ---------------------------------------------------------------------------
// conservative quant kernels: one block per row, plain loops, smem reduction
// v ~= s * (128*a1 + a2)
// ---------------------------------------------------------------------------
__global__ __launch_bounds__(256) void quant_att() {
    int row = blockIdx.x;
    __shared__ float red[256];
    float m = 0.f;
    for (int j = threadIdx.x; j < DD; j += 256) {
        float v = __bfloat162float(g_ashi[(size_t)row * DD + j])
                + __bfloat162float(g_aslo[(size_t)row * DD + j]);
        m = fmaxf(m, fabsf(v));
    }
    red[threadIdx.x] = m;
    __syncthreads();
    for (int s = 128; s > 0; s >>= 1) {
        if (threadIdx.x < s)
            red[threadIdx.x] = fmaxf(red[threadIdx.x], red[threadIdx.x + s]);
        __syncthreads();
    }
    float mx = red[0];
    float inv = mx > 0.f ? 16256.f / mx : 0.f;
    if (threadIdx.x == 0) g_sa[row] = mx > 0.f ? mx / 16256.f : 0.f;
    for (int j = threadIdx.x; j < DD; j += 256) {
        float v = __bfloat162float(g_ashi[(size_t)row * DD + j])
                + __bfloat162float(g_aslo[(size_t)row * DD + j]);
        float ai = rintf(v * inv);
        int a1 = (int)rintf(ai * 0.0078125f);
        int a2 = (int)ai - 128 * a1;
        g_a1[(size_t)row * DD + j] = (int8_t)a1;
        g_a2[(size_t)row * DD + j] = (int8_t)a2;
    }
}

__global__ __launch_bounds__(256) void quant_wo(const float* __restrict__ Wo) {
    int row = blockIdx.x;          // output column n
    __shared__ float red[256];
    float m = 0.f;
    for (int j = threadIdx.x; j < DD; j += 256)
        m = fmaxf(m, fabsf(Wo[(size_t)j * DD + row]));
    red[threadIdx.x] = m;
    __syncthreads();
    for (int s = 128; s > 0; s >>= 1) {
        if (threadIdx.x < s)
            red[threadIdx.x] = fmaxf(red[threadIdx.x], red[threadIdx.x + s]);
        __syncthreads();
    }
    float mx = red[0];
    float inv = mx > 0.f ? 16256.f / mx : 0.f;
    if (threadIdx.x == 0) g_swo[row] = mx > 0.f ? mx / 16256.f : 0.f;
    for (int j = threadIdx.x; j < DD; j += 256) {
        float v = Wo[(size_t)j * DD + row];
        float ai = rintf(v * inv);
        int a1 = (int)rintf(ai * 0.0078125f);
        int a2 = (int)ai - 128 * a1;
        g_wo1[(size_t)row * DD + j] = (int8_t)a1;
        g_wo2[(size_t)row * DD + j] = (int8_t)a2;
    }
}

// ---------------------------------------------------------------------------
// bf16 split GEMM (round-7 verbatim, qkv only):
// C = Ahi.Bhi + Ahi.Blo + Alo.Bhi ; CTA 256x128, warp 64x64, 2-stage
// ---------------------------------------------------------------------------
__global__ __launch_bounds__(256) void gemm_kernel(
    const float* __restrict__ b0, const float* __restrict__ b1,
    const float* __restrict__ b2)
{
    extern __shared__ char smem[];
    const uint32_t sbase = smem_u32(smem);
    const int tid  = threadIdx.x;
    const int lane = tid & 31;
    const int warp = tid >> 5;
    const int wm = warp >> 1;
    const int wn = warp & 1;

    const int bn = blockIdx.x, bm = blockIdx.y;

    const char* Ah = (const char*)(g_xhi + (size_t)bm * 256 * DD);
    const char* Al = (const char*)(g_xlo + (size_t)bm * 256 * DD);
    const char* Bh = (const char*)(g_wqhi + (size_t)bn * 128 * DD);
    const char* Bl = (const char*)(g_wqlo + (size_t)bn * 128 * DD);

    auto load_stage = [&](int kt, int s) {
        uint32_t sb = sbase + s * STG;
        size_t kb = (size_t)kt * 128;
        #pragma unroll
        for (int i = 0; i < 8; i++) {
            int idx = i * 256 + tid;
            int r = idx >> 3, c = idx & 7;
            uint32_t off = SW128(r * 128 + c * 16);
            size_t go = (size_t)r * (DD * 2) + kb + c * 16;
            cp16(sb + S_AHI + off, Ah + go);
            cp16(sb + S_ALO + off, Al + go);
        }
        #pragma unroll
        for (int i = 0; i < 4; i++) {
            int idx = i * 256 + tid;
            int r = idx >> 3, c = idx & 7;
            uint32_t off = SW128(r * 128 + c * 16);
            size_t go = (size_t)r * (DD * 2) + kb + c * 16;
            cp16(sb + S_BHI + off, Bh + go);
            cp16(sb + S_BLO + off, Bl + go);
        }
        cp_commit();
    };

    float acc[4][8][4];
    #pragma unroll
    for (int mi = 0; mi < 4; mi++)
        #pragma unroll
        for (int ni = 0; ni < 8; ni++)
            #pragma unroll
            for (int j = 0; j < 4; j++) acc[mi][ni][j] = 0.f;

    load_stage(0, 0);

    const int a_row = wm * 64 + (lane & 15);
    const int a_chb = (lane >> 4) * 16;
    const int b_row = wn * 64 + (lane & 7) + ((lane >> 3) & 1) * 8;
    const int b_chb = (lane >> 4) * 16;

    for (int kt = 0; kt < NKC; kt++) {
        if (kt + 1 < NKC) {
            load_stage(kt + 1, (kt + 1) & 1);
            cp_wait<1>();
        } else {
            cp_wait<0>();
        }
        __syncthreads();

        uint32_t sb = sbase + (kt & 1) * STG;

        #pragma unroll
        for (int ks = 0; ks < 4; ks++) {
            uint32_t ahi[4][4], alo[4][4], bhi[8][2], blo[8][2];
            #pragma unroll
            for (int mi = 0; mi < 4; mi++)
                ldsm4(ahi[mi][0], ahi[mi][1], ahi[mi][2], ahi[mi][3],
                      sb + S_AHI + SW128((a_row + mi * 16) * 128 + ks * 32 + a_chb));
            #pragma unroll
            for (int p = 0; p < 4; p++) {
                uint32_t r0, r1, r2, r3;
                ldsm4(r0, r1, r2, r3,
                      sb + S_BHI + SW128((b_row + p * 16) * 128 + ks * 32 + b_chb));
                bhi[2*p][0] = r0; bhi[2*p][1] = r2;
                bhi[2*p+1][0] = r1; bhi[2*p+1][1] = r3;
            }
            #pragma unroll
            for (int mi = 0; mi < 4; mi++)
                #pragma unroll
                for (int ni = 0; ni < 8; ni++)
                    mma16816(acc[mi][ni][0], acc[mi][ni][1], acc[mi][ni][2], acc[mi][ni][3],
                             ahi[mi][0], ahi[mi][1], ahi[mi][2], ahi[mi][3],
                             bhi[ni][0], bhi[ni][1]);
            #pragma unroll
            for (int p = 0; p < 4; p++) {
                uint32_t r0, r1, r2, r3;
                ldsm4(r0, r1, r2, r3,
                      sb + S_BLO + SW128((b_row + p * 16) * 128 + ks * 32 + b_chb));
                blo[2*p][0] = r0; blo[2*p][1] = r2;
                blo[2*p+1][0] = r1; blo[2*p+1][1] = r3;
            }
            #pragma unroll
            for (int mi = 0; mi < 4; mi++)
                #pragma unroll
                for (int ni = 0; ni < 8; ni++)
                    mma16816(acc[mi][ni][0], acc[mi][ni][1], acc[mi][ni][2], acc[mi][ni][3],
                             ahi[mi][0], ahi[mi][1], ahi[mi][2], ahi[mi][3],
                             blo[ni][0], blo[ni][1]);
            #pragma unroll
            for (int mi = 0; mi < 4; mi++)
                ldsm4(alo[mi][0], alo[mi][1], alo[mi][2], alo[mi][3],
                      sb + S_ALO + SW128((a_row + mi * 16) * 128 + ks * 32 + a_chb));
            #pragma unroll
            for (int mi = 0; mi < 4; mi++)
                #pragma unroll
                for (int ni = 0; ni < 8; ni++)
                    mma16816(acc[mi][ni][0], acc[mi][ni][1], acc[mi][ni][2], acc[mi][ni][3],
                             alo[mi][0], alo[mi][1], alo[mi][2], alo[mi][3],
                             bhi[ni][0], bhi[ni][1]);
        }
        __syncthreads();
    }

    const int gid = lane >> 2;
    const int tg  = lane & 3;
    #pragma unroll
    for (int mi = 0; mi < 4; mi++) {
        #pragma unroll
        for (int half = 0; half < 2; half++) {
            int m = bm * 256 + wm * 64 + mi * 16 + gid + half * 8;
            #pragma unroll
            for (int ni = 0; ni < 8; ni++) {
                int n = bn * 128 + wn * 64 + ni * 8 + tg * 2;
                float v0 = acc[mi][ni][half * 2 + 0];
                float v1 = acc[mi][ni][half * 2 + 1];
                int which = n / DD;
                int rem = n - which * DD;
                int h = rem >> 6, e = rem & 63;
                const float* bp = ((which == 0) ? b0 : (which == 1) ? b1 : b2) + h * EE + e;
                v0 += bp[0]; v1 += bp[1];
                uint32_t hi = pack_hi(v0, v1);
                uint32_t lo = pack_rn(v0 - trunc_bf(v0), v1 - trunc_bf(v1));
                __nv_bfloat16* ah = (which == 0) ? g_qhi : (which == 1) ? g_khi : g_vhi;
                __nv_bfloat16* al = (which == 0) ? g_qlo : (which == 1) ? g_klo : g_vlo;
                size_t off = (((size_t)(m >> 9) * HH + h) * SS + (m & 511)) * EE + e;
                *(uint32_t*)(ah + off) = hi;
                *(uint32_t*)(al + off) = lo;
            }
        }
    }
}

// ---------------------------------------------------------------------------
// int8 proj GEMM: out = sA*sWo*(16384*A1B1 + 128*(A1B2 + A2B1)) + bo
// CTA 128x64, 8 warps (4x2), warp tile 32x32, 2-stage, k-chunk 128
// ---------------------------------------------------------------------------
__global__ __launch_bounds__(256) void gemm_proj_i8(
    const float* __restrict__ bo, float* __restrict__ out)
{
    extern __shared__ char smem[];
    const uint32_t sbase = smem_u32(smem);
    const int tid  = threadIdx.x;
    const int lane = tid & 31;
    const int warp = tid >> 5;
    const int wm = warp >> 1;        // 0..3
    const int wn = warp & 1;         // 0..1

    const int bn = blockIdx.x, bm = blockIdx.y;

    const char* A1p = (const char*)(g_a1 + (size_t)bm * 128 * DD);
    const char* A2p = (const char*)(g_a2 + (size_t)bm * 128 * DD);
    const char* B1p = (const char*)(g_wo1 + (size_t)bn * 64 * DD);
    const char* B2p = (const char*)(g_wo2 + (size_t)bn * 64 * DD);

    auto load_stage = [&](int kt, int s) {
        uint32_t sb = sbase + s * ISTG;
        size_t kb = (size_t)kt * 128;
        #pragma unroll
        for (int i = 0; i < 4; i++) {
            int idx = i * 256 + tid;
            int r = idx >> 3, c = idx & 7;
            uint32_t off = SW128(r * 128 + c * 16);
            size_t go = (size_t)r * DD + kb + c * 16;
            cp16(sb + I_A1 + off, A1p + go);
            cp16(sb + I_A2 + off, A2p + go);
        }
        #pragma unroll
        for (int i = 0; i < 2; i++) {
            int idx = i * 256 + tid;
            int r = idx >> 3, c = idx & 7;
            uint32_t off = SW128(r * 128 + c * 16);
            size_t go = (size_t)r * DD + kb + c * 16;
            cp16(sb + I_B1 + off, B1p + go);
            cp16(sb + I_B2 + off, B2p + go);
        }
        cp_commit();
    };

    int acc1[2][4][4], acc2[2][4][4];
    #pragma unroll
    for (int mi = 0; mi < 2; mi++)
        #pragma unroll
        for (int ni = 0; ni < 4; ni++)
            #pragma unroll
            for (int j = 0; j < 4; j++) { acc1[mi][ni][j] = 0; acc2[mi][ni][j] = 0; }

    load_stage(0, 0);

    const int a_row = wm * 32 + (lane & 15);
    const int a_chb = (lane >> 4) * 16;
    const int b_row = wn * 32 + (lane & 7) + ((lane >> 3) & 1) * 8;
    const int b_chb = (lane >> 4) * 16;

    for (int kt = 0; kt < NKCI; kt++) {
        if (kt + 1 < NKCI) {
            load_stage(kt + 1, (kt + 1) & 1);
            cp_wait<1>();
        } else {
            cp_wait<0>();
        }
        __syncthreads();

        uint32_t sb = sbase + (kt & 1) * ISTG;

        #pragma unroll
        for (int ks = 0; ks < 4; ks++) {
            uint32_t a1f[2][4], a2f[2][4], b1f[4][2], b2f[4][2];
            #pragma unroll
            for (int mi = 0; mi < 2; mi++)
                ldsm4(a1f[mi][0], a1f[mi][1], a1f[mi][2], a1f[mi][3],
                      sb + I_A1 + SW128((a_row + mi * 16) * 128 + ks * 32 + a_chb));
            #pragma unroll
            for (int p = 0; p < 2; p++) {
                uint32_t r0, r1, r2, r3;
                ldsm4(r0, r1, r2, r3,
                      sb + I_B1 + SW128((b_row + p * 16) * 128 + ks * 32 + b_chb));
                b1f[2*p][0] = r0; b1f[2*p][1] = r2;
                b1f[2*p+1][0] = r1; b1f[2*p+1][1] = r3;
            }
            #pragma unroll
            for (int mi = 0; mi < 2; mi++)
                #pragma unroll
                for (int ni = 0; ni < 4; ni++)
                    imma16832(acc1[mi][ni][0], acc1[mi][ni][1], acc1[mi][ni][2], acc1[mi][ni][3],
                              a1f[mi][0], a1f[mi][1], a1f[mi][2], a1f[mi][3],
                              b1f[ni][0], b1f[ni][1]);
            #pragma unroll
            for (int p = 0; p < 2; p++) {
                uint32_t r0, r1, r2, r3;
                ldsm4(r0, r1, r2, r3,
                      sb + I_B2 + SW128((b_row + p * 16) * 128 + ks * 32 + b_chb));
                b2f[2*p][0] = r0; b2f[2*p][1] = r2;
                b2f[2*p+1][0] = r1; b2f[2*p+1][1] = r3;
            }
            #pragma unroll
            for (int mi = 0; mi < 2; mi++)
                #pragma unroll
                for (int ni = 0; ni < 4; ni++)
                    imma16832(acc2[mi][ni][0], acc2[mi][ni][1], acc2[mi][ni][2], acc2[mi][ni][3],
                              a1f[mi][0], a1f[mi][1], a1f[mi][2], a1f[mi][3],
                              b2f[ni][0], b2f[ni][1]);
            #pragma unroll
            for (int mi = 0; mi < 2; mi++)
                ldsm4(a2f[mi][0], a2f[mi][1], a2f[mi][2], a2f[mi][3],
                      sb + I_A2 + SW128((a_row + mi * 16) * 128 + ks * 32 + a_chb));
            #pragma unroll
            for (int mi = 0; mi < 2; mi++)
                #pragma unroll
                for (int ni = 0; ni < 4; ni++)
                    imma16832(acc2[mi][ni][0], acc2[mi][ni][1], acc2[mi][ni][2], acc2[mi][ni][3],
                              a2f[mi][0], a2f[mi][1], a2f[mi][2], a2f[mi][3],
                              b1f[ni][0], b1f[ni][1]);
        }
        __syncthreads();
    }

    const int gid = lane >> 2;
    const int tg  = lane & 3;
    #pragma unroll
    for (int mi = 0; mi < 2; mi++) {
        #pragma unroll
        for (int half = 0; half < 2; half++) {
            int m = bm * 128 + wm * 32 + mi * 16 + gid + half * 8;
            float sam = g_sa[m];
            #pragma unroll
            for (int ni = 0; ni < 4; ni++) {
                int n = bn * 64 + wn * 32 + ni * 8 + tg * 2;
                float v0 = sam * g_swo[n]
                         * (16384.f * (float)acc1[mi][ni][half * 2 + 0]
                          + 128.f   * (float)acc2[mi][ni][half * 2 + 0]);
                float v1 = sam * g_swo[n + 1]
                         * (16384.f * (float)acc1[mi][ni][half * 2 + 1]
                          + 128.f   * (float)acc2[mi][ni][half * 2 + 1]);
                float2 w; w.x = v0 + bo[n]; w.y = v1 + bo[n + 1];
                *(float2*)(out + (size_t)m * DD + n) = w;
            }
        }
    }
}

// ---------------------------------------------------------------------------
// Tensor-core flash attention (round-7 verbatim)
// ---------------------------------------------------------------------------
#define AT_SMEM (32768 + 2*32768)

__global__ __launch_bounds__(256) void attn_kernel()
{
    extern __shared__ char smem[];
    const uint32_t sb = smem_u32(smem);
    const int tid  = threadIdx.x;
    const int lane = tid & 31;
    const int w    = tid >> 5;

    const int qt = blockIdx.x, h = blockIdx.y, b = blockIdx.z;
    const size_t bh = (size_t)b * HH + h;

    const char* qh_g = (const char*)(g_qhi + (bh * SS + qt * 128) * EE);
    const char* ql_g = (const char*)(g_qlo + (bh * SS + qt * 128) * EE);
    const char* kh_g = (const char*)(g_khi + bh * SS * EE);
    const char* kl_g = (const char*)(g_klo + bh * SS * EE);
    const char* vh_g = (const char*)(g_vhi + bh * SS * EE);
    const char* vl_g = (const char*)(g_vlo + bh * SS * EE);

    #pragma unroll
    for (int i = 0; i < 4; i++) {
        int idx = i * 256 + tid;
        int r = idx >> 3, c = idx & 7;
        cp16(sb + SW128(r * 128 + c * 16), qh_g + (size_t)r * 128 + c * 16);
        cp16(sb + 16384 + SW128(r * 128 + c * 16), ql_g + (size_t)r * 128 + c * 16);
    }

    auto load_kv = [&](int t, int s) {
        uint32_t kb = sb + 32768 + s * 32768;
        size_t rowbase = (size_t)t * 64 * 128;
        #pragma unroll
        for (int i = 0; i < 8; i++) {
            int tile = i >> 1;
            int r = (i & 1) * 32 + (tid >> 3);
            int c = tid & 7;
            const char* src = (tile == 0) ? kh_g : (tile == 1) ? kl_g
                            : (tile == 2) ? vh_g : vl_g;
            cp16(kb + tile * 8192 + SW128(r * 128 + c * 16),
                 src + rowbase + (size_t)r * 128 + c * 16);
        }
    };

    load_kv(0, 0);
    cp_commit();

    float oacc[8][4];
    #pragma unroll
    for (int ni = 0; ni < 8; ni++)
        #pragma unroll
        for (int j = 0; j < 4; j++) oacc[ni][j] = 0.f;
    float m0 = -1e30f, m1 = -1e30f, l0 = 0.f, l1 = 0.f;

    uint32_t qh[4][4], ql[4][4];

    const int krow = (lane & 7) + ((lane >> 3) & 1) * 8;
    const int kch  = (lane >> 4) * 16;

    for (int t = 0; t < 8; t++) {
        cp_wait<0>();
        __syncthreads();

        if (t == 0) {
            #pragma unroll
            for (int ks = 0; ks < 4; ks++) {
                uint32_t ad = SW128((w * 16 + (lane & 15)) * 128 + ks * 32 + (lane >> 4) * 16);
                ldsm4(qh[ks][0], qh[ks][1], qh[ks][2], qh[ks][3], sb + ad);
                ldsm4(ql[ks][0], ql[ks][1], ql[ks][2], ql[ks][3], sb + 16384 + ad);
            }
        }

        if (t < 7) { load_kv(t + 1, (t + 1) & 1); cp_commit(); }
        else       { cp_commit(); }

        uint32_t kb = sb + 32768 + (t & 1) * 32768;

        float sacc[8][4];
        #pragma unroll
        for (int ni = 0; ni < 8; ni++)
            #pragma unroll
            for (int j = 0; j < 4; j++) sacc[ni][j] = 0.f;

        #pragma unroll
        for (int ks = 0; ks < 4; ks++) {
            #pragma unroll
            for (int nj = 0; nj < 4; nj++) {
                uint32_t ad = SW128((nj * 16 + krow) * 128 + ks * 32 + kch);
                uint32_t h0, h1, h2, h3, e0, e1, e2, e3;
                ldsm4(h0, h1, h2, h3, kb + ad);
                ldsm4(e0, e1, e2, e3, kb + 8192 + ad);
                mma16816(sacc[2*nj][0], sacc[2*nj][1], sacc[2*nj][2], sacc[2*nj][3],
                         qh[ks][0], qh[ks][1], qh[ks][2], qh[ks][3], h0, h2);
                mma16816(sacc[2*nj+1][0], sacc[2*nj+1][1], sacc[2*nj+1][2], sacc[2*nj+1][3],
                         qh[ks][0], qh[ks][1], qh[ks][2], qh[ks][3], h1, h3);
                mma16816(sacc[2*nj][0], sacc[2*nj][1], sacc[2*nj][2], sacc[2*nj][3],
                         qh[ks][0], qh[ks][1], qh[ks][2], qh[ks][3], e0, e2);
                mma16816(sacc[2*nj+1][0], sacc[2*nj+1][1], sacc[2*nj+1][2], sacc[2*nj+1][3],
                         qh[ks][0], qh[ks][1], qh[ks][2], qh[ks][3], e1, e3);
                mma16816(sacc[2*nj][0], sacc[2*nj][1], sacc[2*nj][2], sacc[2*nj][3],
                         ql[ks][0], ql[ks][1], ql[ks][2], ql[ks][3], h0, h2);
                mma16816(sacc[2*nj+1][0], sacc[2*nj+1][1], sacc[2*nj+1][2], sacc[2*nj+1][3],
                         ql[ks][0], ql[ks][1], ql[ks][2], ql[ks][3], h1, h3);
            }
        }

        float ml0 = -1e30f, ml1 = -1e30f;
        #pragma unroll
        for (int ni = 0; ni < 8; ni++) {
            sacc[ni][0] *= 0.125f; sacc[ni][1] *= 0.125f;
            sacc[ni][2] *= 0.125f; sacc[ni][3] *= 0.125f;
            ml0 = fmaxf(ml0, fmaxf(sacc[ni][0], sacc[ni][1]));
            ml1 = fmaxf(ml1, fmaxf(sacc[ni][2], sacc[ni][3]));
        }
        ml0 = fmaxf(ml0, __shfl_xor_sync(0xffffffffu, ml0, 1));
        ml0 = fmaxf(ml0, __shfl_xor_sync(0xffffffffu, ml0, 2));
        ml1 = fmaxf(ml1, __shfl_xor_sync(0xffffffffu, ml1, 1));
        ml1 = fmaxf(ml1, __shfl_xor_sync(0xffffffffu, ml1, 2));

        float mn0 = fmaxf(m0, ml0), mn1 = fmaxf(m1, ml1);
        float corr0 = __expf(m0 - mn0), corr1 = __expf(m1 - mn1);
        m0 = mn0; m1 = mn1;

        float rs0 = 0.f, rs1 = 0.f;
        #pragma unroll
        for (int ni = 0; ni < 8; ni++) {
            sacc[ni][0] = __expf(sacc[ni][0] - mn0);
            sacc[ni][1] = __expf(sacc[ni][1] - mn0);
            sacc[ni][2] = __expf(sacc[ni][2] - mn1);
            sacc[ni][3] = __expf(sacc[ni][3] - mn1);
            rs0 += sacc[ni][0] + sacc[ni][1];
            rs1 += sacc[ni][2] + sacc[ni][3];
        }
        rs0 += __shfl_xor_sync(0xffffffffu, rs0, 1);
        rs0 += __shfl_xor_sync(0xffffffffu, rs0, 2);
        rs1 += __shfl_xor_sync(0xffffffffu, rs1, 1);
        rs1 += __shfl_xor_sync(0xffffffffu, rs1, 2);
        l0 = l0 * corr0 + rs0;
        l1 = l1 * corr1 + rs1;
        #pragma unroll
        for (int ni = 0; ni < 8; ni++) {
            oacc[ni][0] *= corr0; oacc[ni][1] *= corr0;
            oacc[ni][2] *= corr1; oacc[ni][3] *= corr1;
        }

        #pragma unroll
        for (int ks = 0; ks < 4; ks++) {
            float* p0 = sacc[2 * ks];
            float* p1 = sacc[2 * ks + 1];
            uint32_t ah0 = pack_hi(p0[0], p0[1]);
            uint32_t ah1 = pack_hi(p0[2], p0[3]);
            uint32_t ah2 = pack_hi(p1[0], p1[1]);
            uint32_t ah3 = pack_hi(p1[2], p1[3]);
            uint32_t al0 = pack_rn(p0[0] - trunc_bf(p0[0]), p0[1] - trunc_bf(p0[1]));
            uint32_t al1 = pack_rn(p0[2] - trunc_bf(p0[2]), p0[3] - trunc_bf(p0[3]));
            uint32_t al2 = pack_rn(p1[0] - trunc_bf(p1[0]), p1[1] - trunc_bf(p1[1]));
            uint32_t al3 = pack_rn(p1[2] - trunc_bf(p1[2]), p1[3] - trunc_bf(p1[3]));
            #pragma unroll
            for (int ep = 0; ep < 4; ep++) {
                uint32_t ad = SW128((ks * 16 + krow) * 128 + ep * 32 + kch);
                uint32_t vh0, vh1, vh2, vh3, vl0_, vl1_, vl2_, vl3_;
                ldsm4t(vh0, vh1, vh2, vh3, kb + 16384 + ad);
                ldsm4t(vl0_, vl1_, vl2_, vl3_, kb + 24576 + ad);
                mma16816(oacc[2*ep][0], oacc[2*ep][1], oacc[2*ep][2], oacc[2*ep][3],
                         ah0, ah1, ah2, ah3, vh0, vh1);
                mma16816(oacc[2*ep+1][0], oacc[2*ep+1][1], oacc[2*ep+1][2], oacc[2*ep+1][3],
                         ah0, ah1, ah2, ah3, vh2, vh3);
                mma16816(oacc[2*ep][0], oacc[2*ep][1], oacc[2*ep][2], oacc[2*ep][3],
                         ah0, ah1, ah2, ah3, vl0_, vl1_);
                mma16816(oacc[2*ep+1][0], oacc[2*ep+1][1], oacc[2*ep+1][2], oacc[2*ep+1][3],
                         ah0, ah1, ah2, ah3, vl2_, vl3_);
                mma16816(oacc[2*ep][0], oacc[2*ep][1], oacc[2*ep][2], oacc[2*ep][3],
                         al0, al1, al2, al3, vh0, vh1);
                mma16816(oacc[2*ep+1][0], oacc[2*ep+1][1], oacc[2*ep+1][2], oacc[2*ep+1][3],
                         al0, al1, al2, al3, vh2, vh3);
            }
        }
    }

    // epilogue (round-7 verbatim): normalize + write hi/lo rows
    float inv0 = 1.f / l0, inv1 = 1.f / l1;
    int mrow = b * SS + qt * 128 + w * 16 + (lane >> 2);
    int colb = h * 64 + (lane & 3) * 2;
    #pragma unroll
    for (int ni = 0; ni < 8; ni++) {
        float v0 = oacc[ni][0] * inv0, v1 = oacc[ni][1] * inv0;
        float v2 = oacc[ni][2] * inv1, v3 = oacc[ni][3] * inv1;
        size_t base0 = (size_t)mrow * DD + colb + ni * 8;
        size_t base1 = (size_t)(mrow + 8) * DD + colb + ni * 8;
        *(uint32_t*)(g_ashi + base0) = pack_hi(v0, v1);
        *(uint32_t*)(g_aslo + base0) = pack_rn(v0 - trunc_bf(v0), v1 - trunc_bf(v1));
        *(uint32_t*)(g_ashi + base1) = pack_hi(v2, v3);
        *(uint32_t*)(g_aslo + base1) = pack_rn(v2 - trunc_bf(v2), v3 - trunc_bf(v3));
    }
}

// ---------------------------------------------------------------------------
extern "C" void kernel_launch(void* const* d_in, const int* in_sizes, int n_in,
                              void* d_out, int out_size)
{
    const float* x  = (const float*)d_in[0];
    const float* Wq = (const float*)d_in[1];
    const float* Wk = (const float*)d_in[2];
    const float* Wv = (const float*)d_in[3];
    const float* bq = (const float*)d_in[4];
    const float* bk = (const float*)d_in[5];
    const float* bv = (const float*)d_in[6];
    const float* Wo = (const float*)d_in[7];
    const float* bo = (const float*)d_in[8];
    float* out = (float*)d_out;

    cudaFuncSetAttribute(gemm_kernel, cudaFuncAttributeMaxDynamicSharedMemorySize, G_SMEM);
    cudaFuncSetAttribute(attn_kernel, cudaFuncAttributeMaxDynamicSharedMemorySize, AT_SMEM);
    cudaFuncSetAttribute(gemm_proj_i8, cudaFuncAttributeMaxDynamicSharedMemorySize, I_SMEM);

    prep_x<<<(M_TOT * DD + 255) / 256, 256>>>(x);
    prep_wqkv<<<(N_QKV * DD + 255) / 256, 256>>>(Wq, Wk, Wv);
    quant_wo<<<DD, 256>>>(Wo);

    gemm_kernel<<<dim3(N_QKV / 128, M_TOT / 256), 256, G_SMEM>>>(bq, bk, bv);

    attn_kernel<<<dim3(SS / 128, HH, BB), 256, AT_SMEM>>>();

    quant_att<<<M_TOT, 256>>>();

    gemm_proj_i8<<<dim3(DD / 64, M_TOT / 128), 256, I_SMEM>>>(bo, out);
}

// round 14
// speedup vs baseline: 1.3593x; 1.3593x over previous
#include <cuda_runtime.h>
#include <cuda_bf16.h>
#include <math.h>
#include <stdint.h>

#define BB 32
#define SS 512
#define DD 768
#define HH 12
#define EE 64

#define M_TOT (BB*SS)        // 16384
#define N_QKV (3*DD)         // 2304
#define NKCI  (DD/128)       // 6 k-chunks of 128 (int8 GEMMs)

// int8 GEMM smem per stage: A1 16K | A2 16K | B1 8K | B2 8K = 48KB, 2 stages
#define I_A1 0
#define I_A2 16384
#define I_B1 32768
#define I_B2 40960
#define ISTG 49152
#define I_SMEM (2*ISTG)      // 96KB

// ---------------- device scratch ----------------
__device__ int8_t g_x1[M_TOT*DD], g_x2[M_TOT*DD];      // x quant
__device__ float  g_sx[M_TOT];
__device__ int8_t g_w1[N_QKV*DD], g_w2[N_QKV*DD];      // qkv W^T quant
__device__ float  g_sw[N_QKV];
__device__ int8_t g_wo1[DD*DD],   g_wo2[DD*DD];        // Wo^T quant
__device__ float  g_swo[DD];
__device__ int8_t g_a1[M_TOT*DD], g_a2[M_TOT*DD];      // attn out quant
__device__ float  g_sa[M_TOT];
__device__ __nv_bfloat16 g_ashi[M_TOT*DD], g_aslo[M_TOT*DD];   // attn out split
__device__ __nv_bfloat16 g_qhi[BB*HH*SS*EE], g_qlo[BB*HH*SS*EE];
__device__ __nv_bfloat16 g_khi[BB*HH*SS*EE], g_klo[BB*HH*SS*EE];
__device__ __nv_bfloat16 g_vhi[BB*HH*SS*EE], g_vlo[BB*HH*SS*EE];

// ---------------- helpers ----------------
#define SW128(o) ((o) ^ (((o) >> 3) & 0x70))

__device__ __forceinline__ uint32_t smem_u32(const void* p) {
    return (uint32_t)__cvta_generic_to_shared(p);
}
__device__ __forceinline__ void cp16(uint32_t dst, const void* src) {
    asm volatile("cp.async.cg.shared.global [%0], [%1], 16;" :: "r"(dst), "l"(src) : "memory");
}
__device__ __forceinline__ void cp_commit() {
    asm volatile("cp.async.commit_group;" ::: "memory");
}
template <int N> __device__ __forceinline__ void cp_wait() {
    asm volatile("cp.async.wait_group %0;" :: "n"(N) : "memory");
}
__device__ __forceinline__ void ldsm4(uint32_t& a, uint32_t& b, uint32_t& c, uint32_t& d,
                                      uint32_t addr) {
    asm volatile("ldmatrix.sync.aligned.m8n8.x4.shared.b16 {%0,%1,%2,%3}, [%4];"
                 : "=r"(a), "=r"(b), "=r"(c), "=r"(d) : "r"(addr));
}
__device__ __forceinline__ void ldsm4t(uint32_t& a, uint32_t& b, uint32_t& c, uint32_t& d,
                                       uint32_t addr) {
    asm volatile("ldmatrix.sync.aligned.m8n8.x4.trans.shared.b16 {%0,%1,%2,%3}, [%4];"
                 : "=r"(a), "=r"(b), "=r"(c), "=r"(d) : "r"(addr));
}
__device__ __forceinline__ void mma16816(float& c0, float& c1, float& c2, float& c3,
                                         uint32_t a0, uint32_t a1, uint32_t a2, uint32_t a3,
                                         uint32_t b0, uint32_t b1) {
    asm volatile(
        "mma.sync.aligned.m16n8k16.row.col.f32.bf16.bf16.f32 "
        "{%0,%1,%2,%3}, {%4,%5,%6,%7}, {%8,%9}, {%0,%1,%2,%3};"
        : "+f"(c0), "+f"(c1), "+f"(c2), "+f"(c3)
        : "r"(a0), "r"(a1), "r"(a2), "r"(a3), "r"(b0), "r"(b1));
}
__device__ __forceinline__ void imma16832(int& c0, int& c1, int& c2, int& c3,
                                          uint32_t a0, uint32_t a1, uint32_t a2, uint32_t a3,
                                          uint32_t b0, uint32_t b1) {
    asm volatile(
        "mma.sync.aligned.m16n8k32.row.col.s32.s8.s8.s32 "
        "{%0,%1,%2,%3}, {%4,%5,%6,%7}, {%8,%9}, {%0,%1,%2,%3};"
        : "+r"(c0), "+r"(c1), "+r"(c2), "+r"(c3)
        : "r"(a0), "r"(a1), "r"(a2), "r"(a3), "r"(b0), "r"(b1));
}
__device__ __forceinline__ uint32_t pack_hi(float v0, float v1) {
    return __byte_perm(__float_as_uint(v0), __float_as_uint(v1), 0x7632);
}
__device__ __forceinline__ float trunc_bf(float v) {
    return __uint_as_float(__float_as_uint(v) & 0xffff0000u);
}
__device__ __forceinline__ uint32_t pack_rn(float l0, float l1) {
    uint32_t r;
    asm("cvt.rn.bf16x2.f32 %0, %1, %2;" : "=r"(r) : "f"(l1), "f"(l0));
    return r;
}

// ---------------------------------------------------------------------------
// conservative quant kernels: one block per row, plain loops, smem reduction
// v ~= s * (128*a1 + a2)
// ---------------------------------------------------------------------------
__global__ __launch_bounds__(256) void quant_x(const float* __restrict__ x) {
    int row = blockIdx.x;
    __shared__ float red[256];
    float m = 0.f;
    for (int j = threadIdx.x; j < DD; j += 256)
        m = fmaxf(m, fabsf(x[(size_t)row * DD + j]));
    red[threadIdx.x] = m;
    __syncthreads();
    for (int s = 128; s > 0; s >>= 1) {
        if (threadIdx.x < s)
            red[threadIdx.x] = fmaxf(red[threadIdx.x], red[threadIdx.x + s]);
        __syncthreads();
    }
    float mx = red[0];
    float inv = mx > 0.f ? 16256.f / mx : 0.f;
    if (threadIdx.x == 0) g_sx[row] = mx > 0.f ? mx / 16256.f : 0.f;
    for (int j = threadIdx.x; j < DD; j += 256) {
        float v = x[(size_t)row * DD + j];
        float ai = rintf(v * inv);
        int a1 = (int)rintf(ai * 0.0078125f);
        int a2 = (int)ai - 128 * a1;
        g_x1[(size_t)row * DD + j] = (int8_t)a1;
        g_x2[(size_t)row * DD + j] = (int8_t)a2;
    }
}

__global__ __launch_bounds__(256) void quant_wqkv(
    const float* __restrict__ Wq, const float* __restrict__ Wk,
    const float* __restrict__ Wv)
{
    int row = blockIdx.x;          // n = which*768 + h*64 + e
    int which = row / DD;
    int rem = row - which * DD;
    int h = rem >> 6, e = rem & 63;
    const float* W = ((which == 0) ? Wq : (which == 1) ? Wk : Wv)
                   + (size_t)h * DD * EE + e;
    __shared__ float red[256];
    float m = 0.f;
    for (int j = threadIdx.x; j < DD; j += 256)
        m = fmaxf(m, fabsf(W[(size_t)j * EE]));
    red[threadIdx.x] = m;
    __syncthreads();
    for (int s = 128; s > 0; s >>= 1) {
        if (threadIdx.x < s)
            red[threadIdx.x] = fmaxf(red[threadIdx.x], red[threadIdx.x + s]);
        __syncthreads();
    }
    float mx = red[0];
    float inv = mx > 0.f ? 16256.f / mx : 0.f;
    if (threadIdx.x == 0) g_sw[row] = mx > 0.f ? mx / 16256.f : 0.f;
    for (int j = threadIdx.x; j < DD; j += 256) {
        float v = W[(size_t)j * EE];
        float ai = rintf(v * inv);
        int a1 = (int)rintf(ai * 0.0078125f);
        int a2 = (int)ai - 128 * a1;
        g_w1[(size_t)row * DD + j] = (int8_t)a1;
        g_w2[(size_t)row * DD + j] = (int8_t)a2;
    }
}

__global__ __launch_bounds__(256) void quant_att() {
    int row = blockIdx.x;
    __shared__ float red[256];
    float m = 0.f;
    for (int j = threadIdx.x; j < DD; j += 256) {
        float v = __bfloat162float(g_ashi[(size_t)row * DD + j])
                + __bfloat162float(g_aslo[(size_t)row * DD + j]);
        m = fmaxf(m, fabsf(v));
    }
    red[threadIdx.x] = m;
    __syncthreads();
    for (int s = 128; s > 0; s >>= 1) {
        if (threadIdx.x < s)
            red[threadIdx.x] = fmaxf(red[threadIdx.x], red[threadIdx.x + s]);
        __syncthreads();
    }
    float mx = red[0];
    float inv = mx > 0.f ? 16256.f / mx : 0.f;
    if (threadIdx.x == 0) g_sa[row] = mx > 0.f ? mx / 16256.f : 0.f;
    for (int j = threadIdx.x; j < DD; j += 256) {
        float v = __bfloat162float(g_ashi[(size_t)row * DD + j])
                + __bfloat162float(g_aslo[(size_t)row * DD + j]);
        float ai = rintf(v * inv);
        int a1 = (int)rintf(ai * 0.0078125f);
        int a2 = (int)ai - 128 * a1;
        g_a1[(size_t)row * DD + j] = (int8_t)a1;
        g_a2[(size_t)row * DD + j] = (int8_t)a2;
    }
}

__global__ __launch_bounds__(256) void quant_wo(const float* __restrict__ Wo) {
    int row = blockIdx.x;          // output column n
    __shared__ float red[256];
    float m = 0.f;
    for (int j = threadIdx.x; j < DD; j += 256)
        m = fmaxf(m, fabsf(Wo[(size_t)j * DD + row]));
    red[threadIdx.x] = m;
    __syncthreads();
    for (int s = 128; s > 0; s >>= 1) {
        if (threadIdx.x < s)
            red[threadIdx.x] = fmaxf(red[threadIdx.x], red[threadIdx.x + s]);
        __syncthreads();
    }
    float mx = red[0];
    float inv = mx > 0.f ? 16256.f / mx : 0.f;
    if (threadIdx.x == 0) g_swo[row] = mx > 0.f ? mx / 16256.f : 0.f;
    for (int j = threadIdx.x; j < DD; j += 256) {
        float v = Wo[(size_t)j * DD + row];
        float ai = rintf(v * inv);
        int a1 = (int)rintf(ai * 0.0078125f);
        int a2 = (int)ai - 128 * a1;
        g_wo1[(size_t)row * DD + j] = (int8_t)a1;
        g_wo2[(size_t)row * DD + j] = (int8_t)a2;
    }
}

// ---------------------------------------------------------------------------
// int8 qkv GEMM: q/k/v = sX*sW*(16384*A1B1 + 128*(A1B2 + A2B1)) + bias
// epilogue writes split-bf16 q/k/v [B,H,S,E]. Structure == gemm_proj_i8.
// CTA 128x64, 8 warps (4x2), warp tile 32x32, 2-stage, k-chunk 128
// ---------------------------------------------------------------------------
__global__ __launch_bounds__(256) void gemm_qkv_i8(
    const float* __restrict__ b0, const float* __restrict__ b1,
    const float* __restrict__ b2)
{
    extern __shared__ char smem[];
    const uint32_t sbase = smem_u32(smem);
    const int tid  = threadIdx.x;
    const int lane = tid & 31;
    const int warp = tid >> 5;
    const int wm = warp >> 1;
    const int wn = warp & 1;

    const int bn = blockIdx.x, bm = blockIdx.y;

    const char* A1p = (const char*)(g_x1 + (size_t)bm * 128 * DD);
    const char* A2p = (const char*)(g_x2 + (size_t)bm * 128 * DD);
    const char* B1p = (const char*)(g_w1 + (size_t)bn * 64 * DD);
    const char* B2p = (const char*)(g_w2 + (size_t)bn * 64 * DD);

    auto load_stage = [&](int kt, int s) {
        uint32_t sb = sbase + s * ISTG;
        size_t kb = (size_t)kt * 128;
        #pragma unroll
        for (int i = 0; i < 4; i++) {
            int idx = i * 256 + tid;
            int r = idx >> 3, c = idx & 7;
            uint32_t off = SW128(r * 128 + c * 16);
            size_t go = (size_t)r * DD + kb + c * 16;
            cp16(sb + I_A1 + off, A1p + go);
            cp16(sb + I_A2 + off, A2p + go);
        }
        #pragma unroll
        for (int i = 0; i < 2; i++) {
            int idx = i * 256 + tid;
            int r = idx >> 3, c = idx & 7;
            uint32_t off = SW128(r * 128 + c * 16);
            size_t go = (size_t)r * DD + kb + c * 16;
            cp16(sb + I_B1 + off, B1p + go);
            cp16(sb + I_B2 + off, B2p + go);
        }
        cp_commit();
    };

    int acc1[2][4][4], acc2[2][4][4];
    #pragma unroll
    for (int mi = 0; mi < 2; mi++)
        #pragma unroll
        for (int ni = 0; ni < 4; ni++)
            #pragma unroll
            for (int j = 0; j < 4; j++) { acc1[mi][ni][j] = 0; acc2[mi][ni][j] = 0; }

    load_stage(0, 0);

    const int a_row = wm * 32 + (lane & 15);
    const int a_chb = (lane >> 4) * 16;
    const int b_row = wn * 32 + (lane & 7) + ((lane >> 3) & 1) * 8;
    const int b_chb = (lane >> 4) * 16;

    for (int kt = 0; kt < NKCI; kt++) {
        if (kt + 1 < NKCI) {
            load_stage(kt + 1, (kt + 1) & 1);
            cp_wait<1>();
        } else {
            cp_wait<0>();
        }
        __syncthreads();

        uint32_t sb = sbase + (kt & 1) * ISTG;

        #pragma unroll
        for (int ks = 0; ks < 4; ks++) {
            uint32_t a1f[2][4], a2f[2][4], b1f[4][2], b2f[4][2];
            #pragma unroll
            for (int mi = 0; mi < 2; mi++)
                ldsm4(a1f[mi][0], a1f[mi][1], a1f[mi][2], a1f[mi][3],
                      sb + I_A1 + SW128((a_row + mi * 16) * 128 + ks * 32 + a_chb));
            #pragma unroll
            for (int p = 0; p < 2; p++) {
                uint32_t r0, r1, r2, r3;
                ldsm4(r0, r1, r2, r3,
                      sb + I_B1 + SW128((b_row + p * 16) * 128 + ks * 32 + b_chb));
                b1f[2*p][0] = r0; b1f[2*p][1] = r2;
                b1f[2*p+1][0] = r1; b1f[2*p+1][1] = r3;
            }
            #pragma unroll
            for (int mi = 0; mi < 2; mi++)
                #pragma unroll
                for (int ni = 0; ni < 4; ni++)
                    imma16832(acc1[mi][ni][0], acc1[mi][ni][1], acc1[mi][ni][2], acc1[mi][ni][3],
                              a1f[mi][0], a1f[mi][1], a1f[mi][2], a1f[mi][3],
                              b1f[ni][0], b1f[ni][1]);
            #pragma unroll
            for (int p = 0; p < 2; p++) {
                uint32_t r0, r1, r2, r3;
                ldsm4(r0, r1, r2, r3,
                      sb + I_B2 + SW128((b_row + p * 16) * 128 + ks * 32 + b_chb));
                b2f[2*p][0] = r0; b2f[2*p][1] = r2;
                b2f[2*p+1][0] = r1; b2f[2*p+1][1] = r3;
            }
            #pragma unroll
            for (int mi = 0; mi < 2; mi++)
                #pragma unroll
                for (int ni = 0; ni < 4; ni++)
                    imma16832(acc2[mi][ni][0], acc2[mi][ni][1], acc2[mi][ni][2], acc2[mi][ni][3],
                              a1f[mi][0], a1f[mi][1], a1f[mi][2], a1f[mi][3],
                              b2f[ni][0], b2f[ni][1]);
            #pragma unroll
            for (int mi = 0; mi < 2; mi++)
                ldsm4(a2f[mi][0], a2f[mi][1], a2f[mi][2], a2f[mi][3],
                      sb + I_A2 + SW128((a_row + mi * 16) * 128 + ks * 32 + a_chb));
            #pragma unroll
            for (int mi = 0; mi < 2; mi++)
                #pragma unroll
                for (int ni = 0; ni < 4; ni++)
                    imma16832(acc2[mi][ni][0], acc2[mi][ni][1], acc2[mi][ni][2], acc2[mi][ni][3],
                              a2f[mi][0], a2f[mi][1], a2f[mi][2], a2f[mi][3],
                              b1f[ni][0], b1f[ni][1]);
        }
        __syncthreads();
    }

    // epilogue: dequant + bias, write split-bf16 q/k/v
    const int gid = lane >> 2;
    const int tg  = lane & 3;
    const int which = (bn * 64) / DD;              // uniform per CTA (64 | 768)
    const float* bp0 = (which == 0) ? b0 : (which == 1) ? b1 : b2;
    __nv_bfloat16* ah = (which == 0) ? g_qhi : (which == 1) ? g_khi : g_vhi;
    __nv_bfloat16* al = (which == 0) ? g_qlo : (which == 1) ? g_klo : g_vlo;
    #pragma unroll
    for (int mi = 0; mi < 2; mi++) {
        #pragma unroll
        for (int half = 0; half < 2; half++) {
            int m = bm * 128 + wm * 32 + mi * 16 + gid + half * 8;
            float sam = g_sx[m];
            #pragma unroll
            for (int ni = 0; ni < 4; ni++) {
                int n = bn * 64 + wn * 32 + ni * 8 + tg * 2;
                int rem = n - which * DD;
                int h = rem >> 6, e = rem & 63;
                float v0 = sam * g_sw[n]
                         * (16384.f * (float)acc1[mi][ni][half * 2 + 0]
                          + 128.f   * (float)acc2[mi][ni][half * 2 + 0])
                         + bp0[h * EE + e];
                float v1 = sam * g_sw[n + 1]
                         * (16384.f * (float)acc1[mi][ni][half * 2 + 1]
                          + 128.f   * (float)acc2[mi][ni][half * 2 + 1])
                         + bp0[h * EE + e + 1];
                size_t off = (((size_t)(m >> 9) * HH + h) * SS + (m & 511)) * EE + e;
                *(uint32_t*)(ah + off) = pack_hi(v0, v1);
                *(uint32_t*)(al + off) = pack_rn(v0 - trunc_bf(v0), v1 - trunc_bf(v1));
            }
        }
    }
}

// ---------------------------------------------------------------------------
// int8 proj GEMM (round-13 verbatim)
// ---------------------------------------------------------------------------
__global__ __launch_bounds__(256) void gemm_proj_i8(
    const float* __restrict__ bo, float* __restrict__ out)
{
    extern __shared__ char smem[];
    const uint32_t sbase = smem_u32(smem);
    const int tid  = threadIdx.x;
    const int lane = tid & 31;
    const int warp = tid >> 5;
    const int wm = warp >> 1;
    const int wn = warp & 1;

    const int bn = blockIdx.x, bm = blockIdx.y;

    const char* A1p = (const char*)(g_a1 + (size_t)bm * 128 * DD);
    const char* A2p = (const char*)(g_a2 + (size_t)bm * 128 * DD);
    const char* B1p = (const char*)(g_wo1 + (size_t)bn * 64 * DD);
    const char* B2p = (const char*)(g_wo2 + (size_t)bn * 64 * DD);

    auto load_stage = [&](int kt, int s) {
        uint32_t sb = sbase + s * ISTG;
        size_t kb = (size_t)kt * 128;
        #pragma unroll
        for (int i = 0; i < 4; i++) {
            int idx = i * 256 + tid;
            int r = idx >> 3, c = idx & 7;
            uint32_t off = SW128(r * 128 + c * 16);
            size_t go = (size_t)r * DD + kb + c * 16;
            cp16(sb + I_A1 + off, A1p + go);
            cp16(sb + I_A2 + off, A2p + go);
        }
        #pragma unroll
        for (int i = 0; i < 2; i++) {
            int idx = i * 256 + tid;
            int r = idx >> 3, c = idx & 7;
            uint32_t off = SW128(r * 128 + c * 16);
            size_t go = (size_t)r * DD + kb + c * 16;
            cp16(sb + I_B1 + off, B1p + go);
            cp16(sb + I_B2 + off, B2p + go);
        }
        cp_commit();
    };

    int acc1[2][4][4], acc2[2][4][4];
    #pragma unroll
    for (int mi = 0; mi < 2; mi++)
        #pragma unroll
        for (int ni = 0; ni < 4; ni++)
            #pragma unroll
            for (int j = 0; j < 4; j++) { acc1[mi][ni][j] = 0; acc2[mi][ni][j] = 0; }

    load_stage(0, 0);

    const int a_row = wm * 32 + (lane & 15);
    const int a_chb = (lane >> 4) * 16;
    const int b_row = wn * 32 + (lane & 7) + ((lane >> 3) & 1) * 8;
    const int b_chb = (lane >> 4) * 16;

    for (int kt = 0; kt < NKCI; kt++) {
        if (kt + 1 < NKCI) {
            load_stage(kt + 1, (kt + 1) & 1);
            cp_wait<1>();
        } else {
            cp_wait<0>();
        }
        __syncthreads();

        uint32_t sb = sbase + (kt & 1) * ISTG;

        #pragma unroll
        for (int ks = 0; ks < 4; ks++) {
            uint32_t a1f[2][4], a2f[2][4], b1f[4][2], b2f[4][2];
            #pragma unroll
            for (int mi = 0; mi < 2; mi++)
                ldsm4(a1f[mi][0], a1f[mi][1], a1f[mi][2], a1f[mi][3],
                      sb + I_A1 + SW128((a_row + mi * 16) * 128 + ks * 32 + a_chb));
            #pragma unroll
            for (int p = 0; p < 2; p++) {
                uint32_t r0, r1, r2, r3;
                ldsm4(r0, r1, r2, r3,
                      sb + I_B1 + SW128((b_row + p * 16) * 128 + ks * 32 + b_chb));
                b1f[2*p][0] = r0; b1f[2*p][1] = r2;
                b1f[2*p+1][0] = r1; b1f[2*p+1][1] = r3;
            }
            #pragma unroll
            for (int mi = 0; mi < 2; mi++)
                #pragma unroll
                for (int ni = 0; ni < 4; ni++)
                    imma16832(acc1[mi][ni][0], acc1[mi][ni][1], acc1[mi][ni][2], acc1[mi][ni][3],
                              a1f[mi][0], a1f[mi][1], a1f[mi][2], a1f[mi][3],
                              b1f[ni][0], b1f[ni][1]);
            #pragma unroll
            for (int p = 0; p < 2; p++) {
                uint32_t r0, r1, r2, r3;
                ldsm4(r0, r1, r2, r3,
                      sb + I_B2 + SW128((b_row + p * 16) * 128 + ks * 32 + b_chb));
                b2f[2*p][0] = r0; b2f[2*p][1] = r2;
                b2f[2*p+1][0] = r1; b2f[2*p+1][1] = r3;
            }
            #pragma unroll
            for (int mi = 0; mi < 2; mi++)
                #pragma unroll
                for (int ni = 0; ni < 4; ni++)
                    imma16832(acc2[mi][ni][0], acc2[mi][ni][1], acc2[mi][ni][2], acc2[mi][ni][3],
                              a1f[mi][0], a1f[mi][1], a1f[mi][2], a1f[mi][3],
                              b2f[ni][0], b2f[ni][1]);
            #pragma unroll
            for (int mi = 0; mi < 2; mi++)
                ldsm4(a2f[mi][0], a2f[mi][1], a2f[mi][2], a2f[mi][3],
                      sb + I_A2 + SW128((a_row + mi * 16) * 128 + ks * 32 + a_chb));
            #pragma unroll
            for (int mi = 0; mi < 2; mi++)
                #pragma unroll
                for (int ni = 0; ni < 4; ni++)
                    imma16832(acc2[mi][ni][0], acc2[mi][ni][1], acc2[mi][ni][2], acc2[mi][ni][3],
                              a2f[mi][0], a2f[mi][1], a2f[mi][2], a2f[mi][3],
                              b1f[ni][0], b1f[ni][1]);
        }
        __syncthreads();
    }

    const int gid = lane >> 2;
    const int tg  = lane & 3;
    #pragma unroll
    for (int mi = 0; mi < 2; mi++) {
        #pragma unroll
        for (int half = 0; half < 2; half++) {
            int m = bm * 128 + wm * 32 + mi * 16 + gid + half * 8;
            float sam = g_sa[m];
            #pragma unroll
            for (int ni = 0; ni < 4; ni++) {
                int n = bn * 64 + wn * 32 + ni * 8 + tg * 2;
                float v0 = sam * g_swo[n]
                         * (16384.f * (float)acc1[mi][ni][half * 2 + 0]
                          + 128.f   * (float)acc2[mi][ni][half * 2 + 0]);
                float v1 = sam * g_swo[n + 1]
                         * (16384.f * (float)acc1[mi][ni][half * 2 + 1]
                          + 128.f   * (float)acc2[mi][ni][half * 2 + 1]);
                float2 w; w.x = v0 + bo[n]; w.y = v1 + bo[n + 1];
                *(float2*)(out + (size_t)m * DD + n) = w;
            }
        }
    }
}

// ---------------------------------------------------------------------------
// Tensor-core flash attention (round-7/13 verbatim)
// ---------------------------------------------------------------------------
#define AT_SMEM (32768 + 2*32768)

__global__ __launch_bounds__(256) void attn_kernel()
{
    extern __shared__ char smem[];
    const uint32_t sb = smem_u32(smem);
    const int tid  = threadIdx.x;
    const int lane = tid & 31;
    const int w    = tid >> 5;

    const int qt = blockIdx.x, h = blockIdx.y, b = blockIdx.z;
    const size_t bh = (size_t)b * HH + h;

    const char* qh_g = (const char*)(g_qhi + (bh * SS + qt * 128) * EE);
    const char* ql_g = (const char*)(g_qlo + (bh * SS + qt * 128) * EE);
    const char* kh_g = (const char*)(g_khi + bh * SS * EE);
    const char* kl_g = (const char*)(g_klo + bh * SS * EE);
    const char* vh_g = (const char*)(g_vhi + bh * SS * EE);
    const char* vl_g = (const char*)(g_vlo + bh * SS * EE);

    #pragma unroll
    for (int i = 0; i < 4; i++) {
        int idx = i * 256 + tid;
        int r = idx >> 3, c = idx & 7;
        cp16(sb + SW128(r * 128 + c * 16), qh_g + (size_t)r * 128 + c * 16);
        cp16(sb + 16384 + SW128(r * 128 + c * 16), ql_g + (size_t)r * 128 + c * 16);
    }

    auto load_kv = [&](int t, int s) {
        uint32_t kb = sb + 32768 + s * 32768;
        size_t rowbase = (size_t)t * 64 * 128;
        #pragma unroll
        for (int i = 0; i < 8; i++) {
            int tile = i >> 1;
            int r = (i & 1) * 32 + (tid >> 3);
            int c = tid & 7;
            const char* src = (tile == 0) ? kh_g : (tile == 1) ? kl_g
                            : (tile == 2) ? vh_g : vl_g;
            cp16(kb + tile * 8192 + SW128(r * 128 + c * 16),
                 src + rowbase + (size_t)r * 128 + c * 16);
        }
    };

    load_kv(0, 0);
    cp_commit();

    float oacc[8][4];
    #pragma unroll
    for (int ni = 0; ni < 8; ni++)
        #pragma unroll
        for (int j = 0; j < 4; j++) oacc[ni][j] = 0.f;
    float m0 = -1e30f, m1 = -1e30f, l0 = 0.f, l1 = 0.f;

    uint32_t qh[4][4], ql[4][4];

    const int krow = (lane & 7) + ((lane >> 3) & 1) * 8;
    const int kch  = (lane >> 4) * 16;

    for (int t = 0; t < 8; t++) {
        cp_wait<0>();
        __syncthreads();

        if (t == 0) {
            #pragma unroll
            for (int ks = 0; ks < 4; ks++) {
                uint32_t ad = SW128((w * 16 + (lane & 15)) * 128 + ks * 32 + (lane >> 4) * 16);
                ldsm4(qh[ks][0], qh[ks][1], qh[ks][2], qh[ks][3], sb + ad);
                ldsm4(ql[ks][0], ql[ks][1], ql[ks][2], ql[ks][3], sb + 16384 + ad);
            }
        }

        if (t < 7) { load_kv(t + 1, (t + 1) & 1); cp_commit(); }
        else       { cp_commit(); }

        uint32_t kb = sb + 32768 + (t & 1) * 32768;

        float sacc[8][4];
        #pragma unroll
        for (int ni = 0; ni < 8; ni++)
            #pragma unroll
            for (int j = 0; j < 4; j++) sacc[ni][j] = 0.f;

        #pragma unroll
        for (int ks = 0; ks < 4; ks++) {
            #pragma unroll
            for (int nj = 0; nj < 4; nj++) {
                uint32_t ad = SW128((nj * 16 + krow) * 128 + ks * 32 + kch);
                uint32_t h0, h1, h2, h3, e0, e1, e2, e3;
                ldsm4(h0, h1, h2, h3, kb + ad);
                ldsm4(e0, e1, e2, e3, kb + 8192 + ad);
                mma16816(sacc[2*nj][0], sacc[2*nj][1], sacc[2*nj][2], sacc[2*nj][3],
                         qh[ks][0], qh[ks][1], qh[ks][2], qh[ks][3], h0, h2);
                mma16816(sacc[2*nj+1][0], sacc[2*nj+1][1], sacc[2*nj+1][2], sacc[2*nj+1][3],
                         qh[ks][0], qh[ks][1], qh[ks][2], qh[ks][3], h1, h3);
                mma16816(sacc[2*nj][0], sacc[2*nj][1], sacc[2*nj][2], sacc[2*nj][3],
                         qh[ks][0], qh[ks][1], qh[ks][2], qh[ks][3], e0, e2);
                mma16816(sacc[2*nj+1][0], sacc[2*nj+1][1], sacc[2*nj+1][2], sacc[2*nj+1][3],
                         qh[ks][0], qh[ks][1], qh[ks][2], qh[ks][3], e1, e3);
                mma16816(sacc[2*nj][0], sacc[2*nj][1], sacc[2*nj][2], sacc[2*nj][3],
                         ql[ks][0], ql[ks][1], ql[ks][2], ql[ks][3], h0, h2);
                mma16816(sacc[2*nj+1][0], sacc[2*nj+1][1], sacc[2*nj+1][2], sacc[2*nj+1][3],
                         ql[ks][0], ql[ks][1], ql[ks][2], ql[ks][3], h1, h3);
            }
        }

        float ml0 = -1e30f, ml1 = -1e30f;
        #pragma unroll
        for (int ni = 0; ni < 8; ni++) {
            sacc[ni][0] *= 0.125f; sacc[ni][1] *= 0.125f;
            sacc[ni][2] *= 0.125f; sacc[ni][3] *= 0.125f;
            ml0 = fmaxf(ml0, fmaxf(sacc[ni][0], sacc[ni][1]));
            ml1 = fmaxf(ml1, fmaxf(sacc[ni][2], sacc[ni][3]));
        }
        ml0 = fmaxf(ml0, __shfl_xor_sync(0xffffffffu, ml0, 1));
        ml0 = fmaxf(ml0, __shfl_xor_sync(0xffffffffu, ml0, 2));
        ml1 = fmaxf(ml1, __shfl_xor_sync(0xffffffffu, ml1, 1));
        ml1 = fmaxf(ml1, __shfl_xor_sync(0xffffffffu, ml1, 2));

        float mn0 = fmaxf(m0, ml0), mn1 = fmaxf(m1, ml1);
        float corr0 = __expf(m0 - mn0), corr1 = __expf(m1 - mn1);
        m0 = mn0; m1 = mn1;

        float rs0 = 0.f, rs1 = 0.f;
        #pragma unroll
        for (int ni = 0; ni < 8; ni++) {
            sacc[ni][0] = __expf(sacc[ni][0] - mn0);
            sacc[ni][1] = __expf(sacc[ni][1] - mn0);
            sacc[ni][2] = __expf(sacc[ni][2] - mn1);
            sacc[ni][3] = __expf(sacc[ni][3] - mn1);
            rs0 += sacc[ni][0] + sacc[ni][1];
            rs1 += sacc[ni][2] + sacc[ni][3];
        }
        rs0 += __shfl_xor_sync(0xffffffffu, rs0, 1);
        rs0 += __shfl_xor_sync(0xffffffffu, rs0, 2);
        rs1 += __shfl_xor_sync(0xffffffffu, rs1, 1);
        rs1 += __shfl_xor_sync(0xffffffffu, rs1, 2);
        l0 = l0 * corr0 + rs0;
        l1 = l1 * corr1 + rs1;
        #pragma unroll
        for (int ni = 0; ni < 8; ni++) {
            oacc[ni][0] *= corr0; oacc[ni][1] *= corr0;
            oacc[ni][2] *= corr1; oacc[ni][3] *= corr1;
        }

        #pragma unroll
        for (int ks = 0; ks < 4; ks++) {
            float* p0 = sacc[2 * ks];
            float* p1 = sacc[2 * ks + 1];
            uint32_t ah0 = pack_hi(p0[0], p0[1]);
            uint32_t ah1 = pack_hi(p0[2], p0[3]);
            uint32_t ah2 = pack_hi(p1[0], p1[1]);
            uint32_t ah3 = pack_hi(p1[2], p1[3]);
            uint32_t al0 = pack_rn(p0[0] - trunc_bf(p0[0]), p0[1] - trunc_bf(p0[1]));
            uint32_t al1 = pack_rn(p0[2] - trunc_bf(p0[2]), p0[3] - trunc_bf(p0[3]));
            uint32_t al2 = pack_rn(p1[0] - trunc_bf(p1[0]), p1[1] - trunc_bf(p1[1]));
            uint32_t al3 = pack_rn(p1[2] - trunc_bf(p1[2]), p1[3] - trunc_bf(p1[3]));
            #pragma unroll
            for (int ep = 0; ep < 4; ep++) {
                uint32_t ad = SW128((ks * 16 + krow) * 128 + ep * 32 + kch);
                uint32_t vh0, vh1, vh2, vh3, vl0_, vl1_, vl2_, vl3_;
                ldsm4t(vh0, vh1, vh2, vh3, kb + 16384 + ad);
                ldsm4t(vl0_, vl1_, vl2_, vl3_, kb + 24576 + ad);
                mma16816(oacc[2*ep][0], oacc[2*ep][1], oacc[2*ep][2], oacc[2*ep][3],
                         ah0, ah1, ah2, ah3, vh0, vh1);
                mma16816(oacc[2*ep+1][0], oacc[2*ep+1][1], oacc[2*ep+1][2], oacc[2*ep+1][3],
                         ah0, ah1, ah2, ah3, vh2, vh3);
                mma16816(oacc[2*ep][0], oacc[2*ep][1], oacc[2*ep][2], oacc[2*ep][3],
                         ah0, ah1, ah2, ah3, vl0_, vl1_);
                mma16816(oacc[2*ep+1][0], oacc[2*ep+1][1], oacc[2*ep+1][2], oacc[2*ep+1][3],
                         ah0, ah1, ah2, ah3, vl2_, vl3_);
                mma16816(oacc[2*ep][0], oacc[2*ep][1], oacc[2*ep][2], oacc[2*ep][3],
                         al0, al1, al2, al3, vh0, vh1);
                mma16816(oacc[2*ep+1][0], oacc[2*ep+1][1], oacc[2*ep+1][2], oacc[2*ep+1][3],
                         al0, al1, al2, al3, vh2, vh3);
            }
        }
    }

    float inv0 = 1.f / l0, inv1 = 1.f / l1;
    int mrow = b * SS + qt * 128 + w * 16 + (lane >> 2);
    int colb = h * 64 + (lane & 3) * 2;
    #pragma unroll
    for (int ni = 0; ni < 8; ni++) {
        float v0 = oacc[ni][0] * inv0, v1 = oacc[ni][1] * inv0;
        float v2 = oacc[ni][2] * inv1, v3 = oacc[ni][3] * inv1;
        size_t base0 = (size_t)mrow * DD + colb + ni * 8;
        size_t base1 = (size_t)(mrow + 8) * DD + colb + ni * 8;
        *(uint32_t*)(g_ashi + base0) = pack_hi(v0, v1);
        *(uint32_t*)(g_aslo + base0) = pack_rn(v0 - trunc_bf(v0), v1 - trunc_bf(v1));
        *(uint32_t*)(g_ashi + base1) = pack_hi(v2, v3);
        *(uint32_t*)(g_aslo + base1) = pack_rn(v2 - trunc_bf(v2), v3 - trunc_bf(v3));
    }
}

// ---------------------------------------------------------------------------
extern "C" void kernel_launch(void* const* d_in, const int* in_sizes, int n_in,
                              void* d_out, int out_size)
{
    const float* x  = (const float*)d_in[0];
    const float* Wq = (const float*)d_in[1];
    const float* Wk = (const float*)d_in[2];
    const float* Wv = (const float*)d_in[3];
    const float* bq = (const float*)d_in[4];
    const float* bk = (const float*)d_in[5];
    const float* bv = (const float*)d_in[6];
    const float* Wo = (const float*)d_in[7];
    const float* bo = (const float*)d_in[8];
    float* out = (float*)d_out;

    cudaFuncSetAttribute(gemm_qkv_i8, cudaFuncAttributeMaxDynamicSharedMemorySize, I_SMEM);
    cudaFuncSetAttribute(gemm_proj_i8, cudaFuncAttributeMaxDynamicSharedMemorySize, I_SMEM);
    cudaFuncSetAttribute(attn_kernel, cudaFuncAttributeMaxDynamicSharedMemorySize, AT_SMEM);

    quant_x<<<M_TOT, 256>>>(x);
    quant_wqkv<<<N_QKV, 256>>>(Wq, Wk, Wv);
    quant_wo<<<DD, 256>>>(Wo);

    gemm_qkv_i8<<<dim3(N_QKV / 64, M_TOT / 128), 256, I_SMEM>>>(bq, bk, bv);

    attn_kernel<<<dim3(SS / 128, HH, BB), 256, AT_SMEM>>>();

    quant_att<<<M_TOT, 256>>>();

    gemm_proj_i8<<<dim3(DD / 64, M_TOT / 128), 256, I_SMEM>>>(bo, out);
}

// round 15
// speedup vs baseline: 1.4091x; 1.0366x over previous
#include <cuda_runtime.h>
#include <cuda_bf16.h>
#include <math.h>
#include <stdint.h>

#define BB 32
#define SS 512
#define DD 768
#define HH 12
#define EE 64

#define M_TOT (BB*SS)        // 16384
#define N_QKV (3*DD)         // 2304
#define NKCI  (DD/128)       // 6 k-chunks of 128 (int8 GEMMs)

// int8 GEMM smem per stage (CTA tile 64x128):
// A1 8K | A2 8K | B1 16K | B2 16K = 48KB, 2 stages
#define I_A1 0
#define I_A2 8192
#define I_B1 16384
#define I_B2 32768
#define ISTG 49152
#define I_SMEM (2*ISTG)      // 96KB

// ---------------- device scratch ----------------
__device__ int8_t g_x1[M_TOT*DD], g_x2[M_TOT*DD];      // x quant
__device__ float  g_sx[M_TOT];
__device__ int8_t g_w1[N_QKV*DD], g_w2[N_QKV*DD];      // qkv W^T quant
__device__ float  g_sw[N_QKV];
__device__ int8_t g_wo1[DD*DD],   g_wo2[DD*DD];        // Wo^T quant
__device__ float  g_swo[DD];
__device__ int8_t g_a1[M_TOT*DD], g_a2[M_TOT*DD];      // attn out quant
__device__ float  g_sa[M_TOT];
__device__ __nv_bfloat16 g_ashi[M_TOT*DD], g_aslo[M_TOT*DD];   // attn out split
__device__ __nv_bfloat16 g_qhi[BB*HH*SS*EE], g_qlo[BB*HH*SS*EE];
__device__ __nv_bfloat16 g_khi[BB*HH*SS*EE], g_klo[BB*HH*SS*EE];
__device__ __nv_bfloat16 g_vhi[BB*HH*SS*EE], g_vlo[BB*HH*SS*EE];

// ---------------- helpers ----------------
#define SW128(o) ((o) ^ (((o) >> 3) & 0x70))

__device__ __forceinline__ uint32_t smem_u32(const void* p) {
    return (uint32_t)__cvta_generic_to_shared(p);
}
__device__ __forceinline__ void cp16(uint32_t dst, const void* src) {
    asm volatile("cp.async.cg.shared.global [%0], [%1], 16;" :: "r"(dst), "l"(src) : "memory");
}
__device__ __forceinline__ void cp_commit() {
    asm volatile("cp.async.commit_group;" ::: "memory");
}
template <int N> __device__ __forceinline__ void cp_wait() {
    asm volatile("cp.async.wait_group %0;" :: "n"(N) : "memory");
}
__device__ __forceinline__ void ldsm4(uint32_t& a, uint32_t& b, uint32_t& c, uint32_t& d,
                                      uint32_t addr) {
    asm volatile("ldmatrix.sync.aligned.m8n8.x4.shared.b16 {%0,%1,%2,%3}, [%4];"
                 : "=r"(a), "=r"(b), "=r"(c), "=r"(d) : "r"(addr));
}
__device__ __forceinline__ void ldsm4t(uint32_t& a, uint32_t& b, uint32_t& c, uint32_t& d,
                                       uint32_t addr) {
    asm volatile("ldmatrix.sync.aligned.m8n8.x4.trans.shared.b16 {%0,%1,%2,%3}, [%4];"
                 : "=r"(a), "=r"(b), "=r"(c), "=r"(d) : "r"(addr));
}
__device__ __forceinline__ void mma16816(float& c0, float& c1, float& c2, float& c3,
                                         uint32_t a0, uint32_t a1, uint32_t a2, uint32_t a3,
                                         uint32_t b0, uint32_t b1) {
    asm volatile(
        "mma.sync.aligned.m16n8k16.row.col.f32.bf16.bf16.f32 "
        "{%0,%1,%2,%3}, {%4,%5,%6,%7}, {%8,%9}, {%0,%1,%2,%3};"
        : "+f"(c0), "+f"(c1), "+f"(c2), "+f"(c3)
        : "r"(a0), "r"(a1), "r"(a2), "r"(a3), "r"(b0), "r"(b1));
}
__device__ __forceinline__ void imma16832(int& c0, int& c1, int& c2, int& c3,
                                          uint32_t a0, uint32_t a1, uint32_t a2, uint32_t a3,
                                          uint32_t b0, uint32_t b1) {
    asm volatile(
        "mma.sync.aligned.m16n8k32.row.col.s32.s8.s8.s32 "
        "{%0,%1,%2,%3}, {%4,%5,%6,%7}, {%8,%9}, {%0,%1,%2,%3};"
        : "+r"(c0), "+r"(c1), "+r"(c2), "+r"(c3)
        : "r"(a0), "r"(a1), "r"(a2), "r"(a3), "r"(b0), "r"(b1));
}
__device__ __forceinline__ uint32_t pack_hi(float v0, float v1) {
    return __byte_perm(__float_as_uint(v0), __float_as_uint(v1), 0x7632);
}
__device__ __forceinline__ float trunc_bf(float v) {
    return __uint_as_float(__float_as_uint(v) & 0xffff0000u);
}
__device__ __forceinline__ uint32_t pack_rn(float l0, float l1) {
    uint32_t r;
    asm("cvt.rn.bf16x2.f32 %0, %1, %2;" : "=r"(r) : "f"(l1), "f"(l0));
    return r;
}

// ---------------------------------------------------------------------------
// single-pass quant kernels: 768 elems/row = 3 named scalars per thread
// v ~= s * (128*a1 + a2)
// ---------------------------------------------------------------------------
#define QSPLIT(V, INV, OUT1, OUT2, IDX) do { \
        float ai_ = rintf((V) * (INV)); \
        int a1_ = (int)rintf(ai_ * 0.0078125f); \
        int a2_ = (int)ai_ - 128 * a1_; \
        OUT1[IDX] = (int8_t)a1_; \
        OUT2[IDX] = (int8_t)a2_; \
    } while (0)

__global__ __launch_bounds__(256) void quant_x(const float* __restrict__ x) {
    int row = blockIdx.x;
    int t = threadIdx.x;
    __shared__ float red[256];
    float v0 = x[(size_t)row * DD + t];
    float v1 = x[(size_t)row * DD + t + 256];
    float v2 = x[(size_t)row * DD + t + 512];
    float m = fmaxf(fabsf(v0), fmaxf(fabsf(v1), fabsf(v2)));
    red[t] = m;
    __syncthreads();
    for (int s = 128; s > 0; s >>= 1) {
        if (t < s) red[t] = fmaxf(red[t], red[t + s]);
        __syncthreads();
    }
    float mx = red[0];
    float inv = mx > 0.f ? 16256.f / mx : 0.f;
    if (t == 0) g_sx[row] = mx > 0.f ? mx / 16256.f : 0.f;
    QSPLIT(v0, inv, g_x1, g_x2, (size_t)row * DD + t);
    QSPLIT(v1, inv, g_x1, g_x2, (size_t)row * DD + t + 256);
    QSPLIT(v2, inv, g_x1, g_x2, (size_t)row * DD + t + 512);
}

__global__ __launch_bounds__(256) void quant_wqkv(
    const float* __restrict__ Wq, const float* __restrict__ Wk,
    const float* __restrict__ Wv)
{
    int row = blockIdx.x;          // n = which*768 + h*64 + e
    int t = threadIdx.x;
    int which = row / DD;
    int rem = row - which * DD;
    int h = rem >> 6, e = rem & 63;
    const float* W = ((which == 0) ? Wq : (which == 1) ? Wk : Wv)
                   + (size_t)h * DD * EE + e;
    __shared__ float red[256];
    float v0 = W[(size_t)t * EE];
    float v1 = W[(size_t)(t + 256) * EE];
    float v2 = W[(size_t)(t + 512) * EE];
    float m = fmaxf(fabsf(v0), fmaxf(fabsf(v1), fabsf(v2)));
    red[t] = m;
    __syncthreads();
    for (int s = 128; s > 0; s >>= 1) {
        if (t < s) red[t] = fmaxf(red[t], red[t + s]);
        __syncthreads();
    }
    float mx = red[0];
    float inv = mx > 0.f ? 16256.f / mx : 0.f;
    if (t == 0) g_sw[row] = mx > 0.f ? mx / 16256.f : 0.f;
    QSPLIT(v0, inv, g_w1, g_w2, (size_t)row * DD + t);
    QSPLIT(v1, inv, g_w1, g_w2, (size_t)row * DD + t + 256);
    QSPLIT(v2, inv, g_w1, g_w2, (size_t)row * DD + t + 512);
}

__global__ __launch_bounds__(256) void quant_att() {
    int row = blockIdx.x;
    int t = threadIdx.x;
    __shared__ float red[256];
    float v0 = __bfloat162float(g_ashi[(size_t)row * DD + t])
             + __bfloat162float(g_aslo[(size_t)row * DD + t]);
    float v1 = __bfloat162float(g_ashi[(size_t)row * DD + t + 256])
             + __bfloat162float(g_aslo[(size_t)row * DD + t + 256]);
    float v2 = __bfloat162float(g_ashi[(size_t)row * DD + t + 512])
             + __bfloat162float(g_aslo[(size_t)row * DD + t + 512]);
    float m = fmaxf(fabsf(v0), fmaxf(fabsf(v1), fabsf(v2)));
    red[t] = m;
    __syncthreads();
    for (int s = 128; s > 0; s >>= 1) {
        if (t < s) red[t] = fmaxf(red[t], red[t + s]);
        __syncthreads();
    }
    float mx = red[0];
    float inv = mx > 0.f ? 16256.f / mx : 0.f;
    if (t == 0) g_sa[row] = mx > 0.f ? mx / 16256.f : 0.f;
    QSPLIT(v0, inv, g_a1, g_a2, (size_t)row * DD + t);
    QSPLIT(v1, inv, g_a1, g_a2, (size_t)row * DD + t + 256);
    QSPLIT(v2, inv, g_a1, g_a2, (size_t)row * DD + t + 512);
}

__global__ __launch_bounds__(256) void quant_wo(const float* __restrict__ Wo) {
    int row = blockIdx.x;          // output column n
    int t = threadIdx.x;
    __shared__ float red[256];
    float v0 = Wo[(size_t)t * DD + row];
    float v1 = Wo[(size_t)(t + 256) * DD + row];
    float v2 = Wo[(size_t)(t + 512) * DD + row];
    float m = fmaxf(fabsf(v0), fmaxf(fabsf(v1), fabsf(v2)));
    red[t] = m;
    __syncthreads();
    for (int s = 128; s > 0; s >>= 1) {
        if (t < s) red[t] = fmaxf(red[t], red[t + s]);
        __syncthreads();
    }
    float mx = red[0];
    float inv = mx > 0.f ? 16256.f / mx : 0.f;
    if (t == 0) g_swo[row] = mx > 0.f ? mx / 16256.f : 0.f;
    QSPLIT(v0, inv, g_wo1, g_wo2, (size_t)row * DD + t);
    QSPLIT(v1, inv, g_wo1, g_wo2, (size_t)row * DD + t + 256);
    QSPLIT(v2, inv, g_wo1, g_wo2, (size_t)row * DD + t + 512);
}

// ---------------------------------------------------------------------------
// split-int8 IMMA GEMM core: CTA 64x128, 128 threads (2x2 warps, warp 32x64),
// 2-stage cp.async, k-chunk 128.
// C = sA*sB*(16384*A1B1 + 128*(A1B2 + A2B1))
// ---------------------------------------------------------------------------
__global__ __launch_bounds__(128) void gemm_qkv_i8(
    const float* __restrict__ b0, const float* __restrict__ b1,
    const float* __restrict__ b2)
{
    extern __shared__ char smem[];
    const uint32_t sbase = smem_u32(smem);
    const int tid  = threadIdx.x;
    const int lane = tid & 31;
    const int warp = tid >> 5;
    const int wm = warp >> 1;        // 0..1 (m 32)
    const int wn = warp & 1;         // 0..1 (n 64)

    const int bn = blockIdx.x, bm = blockIdx.y;

    const char* A1p = (const char*)(g_x1 + (size_t)bm * 64 * DD);
    const char* A2p = (const char*)(g_x2 + (size_t)bm * 64 * DD);
    const char* B1p = (const char*)(g_w1 + (size_t)bn * 128 * DD);
    const char* B2p = (const char*)(g_w2 + (size_t)bn * 128 * DD);

    auto load_stage = [&](int kt, int s) {
        uint32_t sb = sbase + s * ISTG;
        size_t kb = (size_t)kt * 128;
        #pragma unroll
        for (int i = 0; i < 4; i++) {           // A: 64 rows x 8 chunks per array
            int idx = i * 128 + tid;
            int r = idx >> 3, c = idx & 7;
            uint32_t off = SW128(r * 128 + c * 16);
            size_t go = (size_t)r * DD + kb + c * 16;
            cp16(sb + I_A1 + off, A1p + go);
            cp16(sb + I_A2 + off, A2p + go);
        }
        #pragma unroll
        for (int i = 0; i < 8; i++) {           // B: 128 rows x 8 chunks per array
            int idx = i * 128 + tid;
            int r = idx >> 3, c = idx & 7;
            uint32_t off = SW128(r * 128 + c * 16);
            size_t go = (size_t)r * DD + kb + c * 16;
            cp16(sb + I_B1 + off, B1p + go);
            cp16(sb + I_B2 + off, B2p + go);
        }
        cp_commit();
    };

    int acc1[2][8][4], acc2[2][8][4];
    #pragma unroll
    for (int mi = 0; mi < 2; mi++)
        #pragma unroll
        for (int ni = 0; ni < 8; ni++)
            #pragma unroll
            for (int j = 0; j < 4; j++) { acc1[mi][ni][j] = 0; acc2[mi][ni][j] = 0; }

    load_stage(0, 0);

    const int a_row = wm * 32 + (lane & 15);
    const int a_chb = (lane >> 4) * 16;
    const int b_row = wn * 64 + (lane & 7) + ((lane >> 3) & 1) * 8;
    const int b_chb = (lane >> 4) * 16;

    for (int kt = 0; kt < NKCI; kt++) {
        if (kt + 1 < NKCI) {
            load_stage(kt + 1, (kt + 1) & 1);
            cp_wait<1>();
        } else {
            cp_wait<0>();
        }
        __syncthreads();

        uint32_t sb = sbase + (kt & 1) * ISTG;

        #pragma unroll
        for (int ks = 0; ks < 4; ks++) {
            uint32_t a1f[2][4], a2f[2][4], b1f[8][2], b2f[8][2];
            #pragma unroll
            for (int mi = 0; mi < 2; mi++)
                ldsm4(a1f[mi][0], a1f[mi][1], a1f[mi][2], a1f[mi][3],
                      sb + I_A1 + SW128((a_row + mi * 16) * 128 + ks * 32 + a_chb));
            #pragma unroll
            for (int p = 0; p < 4; p++) {
                uint32_t r0, r1, r2, r3;
                ldsm4(r0, r1, r2, r3,
                      sb + I_B1 + SW128((b_row + p * 16) * 128 + ks * 32 + b_chb));
                b1f[2*p][0] = r0; b1f[2*p][1] = r2;
                b1f[2*p+1][0] = r1; b1f[2*p+1][1] = r3;
            }
            #pragma unroll
            for (int mi = 0; mi < 2; mi++)
                #pragma unroll
                for (int ni = 0; ni < 8; ni++)
                    imma16832(acc1[mi][ni][0], acc1[mi][ni][1], acc1[mi][ni][2], acc1[mi][ni][3],
                              a1f[mi][0], a1f[mi][1], a1f[mi][2], a1f[mi][3],
                              b1f[ni][0], b1f[ni][1]);
            #pragma unroll
            for (int p = 0; p < 4; p++) {
                uint32_t r0, r1, r2, r3;
                ldsm4(r0, r1, r2, r3,
                      sb + I_B2 + SW128((b_row + p * 16) * 128 + ks * 32 + b_chb));
                b2f[2*p][0] = r0; b2f[2*p][1] = r2;
                b2f[2*p+1][0] = r1; b2f[2*p+1][1] = r3;
            }
            #pragma unroll
            for (int mi = 0; mi < 2; mi++)
                #pragma unroll
                for (int ni = 0; ni < 8; ni++)
                    imma16832(acc2[mi][ni][0], acc2[mi][ni][1], acc2[mi][ni][2], acc2[mi][ni][3],
                              a1f[mi][0], a1f[mi][1], a1f[mi][2], a1f[mi][3],
                              b2f[ni][0], b2f[ni][1]);
            #pragma unroll
            for (int mi = 0; mi < 2; mi++)
                ldsm4(a2f[mi][0], a2f[mi][1], a2f[mi][2], a2f[mi][3],
                      sb + I_A2 + SW128((a_row + mi * 16) * 128 + ks * 32 + a_chb));
            #pragma unroll
            for (int mi = 0; mi < 2; mi++)
                #pragma unroll
                for (int ni = 0; ni < 8; ni++)
                    imma16832(acc2[mi][ni][0], acc2[mi][ni][1], acc2[mi][ni][2], acc2[mi][ni][3],
                              a2f[mi][0], a2f[mi][1], a2f[mi][2], a2f[mi][3],
                              b1f[ni][0], b1f[ni][1]);
        }
        __syncthreads();
    }

    // epilogue: dequant + bias, write split-bf16 q/k/v
    const int gid = lane >> 2;
    const int tg  = lane & 3;
    const int which = (bn * 128) / DD;             // uniform per CTA (128 | 768)
    const float* bp0 = (which == 0) ? b0 : (which == 1) ? b1 : b2;
    __nv_bfloat16* ah = (which == 0) ? g_qhi : (which == 1) ? g_khi : g_vhi;
    __nv_bfloat16* al = (which == 0) ? g_qlo : (which == 1) ? g_klo : g_vlo;
    #pragma unroll
    for (int mi = 0; mi < 2; mi++) {
        #pragma unroll
        for (int half = 0; half < 2; half++) {
            int m = bm * 64 + wm * 32 + mi * 16 + gid + half * 8;
            float sam = g_sx[m];
            #pragma unroll
            for (int ni = 0; ni < 8; ni++) {
                int n = bn * 128 + wn * 64 + ni * 8 + tg * 2;
                int rem = n - which * DD;
                int h = rem >> 6, e = rem & 63;
                float v0 = sam * g_sw[n]
                         * (16384.f * (float)acc1[mi][ni][half * 2 + 0]
                          + 128.f   * (float)acc2[mi][ni][half * 2 + 0])
                         + bp0[h * EE + e];
                float v1 = sam * g_sw[n + 1]
                         * (16384.f * (float)acc1[mi][ni][half * 2 + 1]
                          + 128.f   * (float)acc2[mi][ni][half * 2 + 1])
                         + bp0[h * EE + e + 1];
                size_t off = (((size_t)(m >> 9) * HH + h) * SS + (m & 511)) * EE + e;
                *(uint32_t*)(ah + off) = pack_hi(v0, v1);
                *(uint32_t*)(al + off) = pack_rn(v0 - trunc_bf(v0), v1 - trunc_bf(v1));
            }
        }
    }
}

__global__ __launch_bounds__(128) void gemm_proj_i8(
    const float* __restrict__ bo, float* __restrict__ out)
{
    extern __shared__ char smem[];
    const uint32_t sbase = smem_u32(smem);
    const int tid  = threadIdx.x;
    const int lane = tid & 31;
    const int warp = tid >> 5;
    const int wm = warp >> 1;
    const int wn = warp & 1;

    const int bn = blockIdx.x, bm = blockIdx.y;

    const char* A1p = (const char*)(g_a1 + (size_t)bm * 64 * DD);
    const char* A2p = (const char*)(g_a2 + (size_t)bm * 64 * DD);
    const char* B1p = (const char*)(g_wo1 + (size_t)bn * 128 * DD);
    const char* B2p = (const char*)(g_wo2 + (size_t)bn * 128 * DD);

    auto load_stage = [&](int kt, int s) {
        uint32_t sb = sbase + s * ISTG;
        size_t kb = (size_t)kt * 128;
        #pragma unroll
        for (int i = 0; i < 4; i++) {
            int idx = i * 128 + tid;
            int r = idx >> 3, c = idx & 7;
            uint32_t off = SW128(r * 128 + c * 16);
            size_t go = (size_t)r * DD + kb + c * 16;
            cp16(sb + I_A1 + off, A1p + go);
            cp16(sb + I_A2 + off, A2p + go);
        }
        #pragma unroll
        for (int i = 0; i < 8; i++) {
            int idx = i * 128 + tid;
            int r = idx >> 3, c = idx & 7;
            uint32_t off = SW128(r * 128 + c * 16);
            size_t go = (size_t)r * DD + kb + c * 16;
            cp16(sb + I_B1 + off, B1p + go);
            cp16(sb + I_B2 + off, B2p + go);
        }
        cp_commit();
    };

    int acc1[2][8][4], acc2[2][8][4];
    #pragma unroll
    for (int mi = 0; mi < 2; mi++)
        #pragma unroll
        for (int ni = 0; ni < 8; ni++)
            #pragma unroll
            for (int j = 0; j < 4; j++) { acc1[mi][ni][j] = 0; acc2[mi][ni][j] = 0; }

    load_stage(0, 0);

    const int a_row = wm * 32 + (lane & 15);
    const int a_chb = (lane >> 4) * 16;
    const int b_row = wn * 64 + (lane & 7) + ((lane >> 3) & 1) * 8;
    const int b_chb = (lane >> 4) * 16;

    for (int kt = 0; kt < NKCI; kt++) {
        if (kt + 1 < NKCI) {
            load_stage(kt + 1, (kt + 1) & 1);
            cp_wait<1>();
        } else {
            cp_wait<0>();
        }
        __syncthreads();

        uint32_t sb = sbase + (kt & 1) * ISTG;

        #pragma unroll
        for (int ks = 0; ks < 4; ks++) {
            uint32_t a1f[2][4], a2f[2][4], b1f[8][2], b2f[8][2];
            #pragma unroll
            for (int mi = 0; mi < 2; mi++)
                ldsm4(a1f[mi][0], a1f[mi][1], a1f[mi][2], a1f[mi][3],
                      sb + I_A1 + SW128((a_row + mi * 16) * 128 + ks * 32 + a_chb));
            #pragma unroll
            for (int p = 0; p < 4; p++) {
                uint32_t r0, r1, r2, r3;
                ldsm4(r0, r1, r2, r3,
                      sb + I_B1 + SW128((b_row + p * 16) * 128 + ks * 32 + b_chb));
                b1f[2*p][0] = r0; b1f[2*p][1] = r2;
                b1f[2*p+1][0] = r1; b1f[2*p+1][1] = r3;
            }
            #pragma unroll
            for (int mi = 0; mi < 2; mi++)
                #pragma unroll
                for (int ni = 0; ni < 8; ni++)
                    imma16832(acc1[mi][ni][0], acc1[mi][ni][1], acc1[mi][ni][2], acc1[mi][ni][3],
                              a1f[mi][0], a1f[mi][1], a1f[mi][2], a1f[mi][3],
                              b1f[ni][0], b1f[ni][1]);
            #pragma unroll
            for (int p = 0; p < 4; p++) {
                uint32_t r0, r1, r2, r3;
                ldsm4(r0, r1, r2, r3,
                      sb + I_B2 + SW128((b_row + p * 16) * 128 + ks * 32 + b_chb));
                b2f[2*p][0] = r0; b2f[2*p][1] = r2;
                b2f[2*p+1][0] = r1; b2f[2*p+1][1] = r3;
            }
            #pragma unroll
            for (int mi = 0; mi < 2; mi++)
                #pragma unroll
                for (int ni = 0; ni < 8; ni++)
                    imma16832(acc2[mi][ni][0], acc2[mi][ni][1], acc2[mi][ni][2], acc2[mi][ni][3],
                              a1f[mi][0], a1f[mi][1], a1f[mi][2], a1f[mi][3],
                              b2f[ni][0], b2f[ni][1]);
            #pragma unroll
            for (int mi = 0; mi < 2; mi++)
                ldsm4(a2f[mi][0], a2f[mi][1], a2f[mi][2], a2f[mi][3],
                      sb + I_A2 + SW128((a_row + mi * 16) * 128 + ks * 32 + a_chb));
            #pragma unroll
            for (int mi = 0; mi < 2; mi++)
                #pragma unroll
                for (int ni = 0; ni < 8; ni++)
                    imma16832(acc2[mi][ni][0], acc2[mi][ni][1], acc2[mi][ni][2], acc2[mi][ni][3],
                              a2f[mi][0], a2f[mi][1], a2f[mi][2], a2f[mi][3],
                              b1f[ni][0], b1f[ni][1]);
        }
        __syncthreads();
    }

    const int gid = lane >> 2;
    const int tg  = lane & 3;
    #pragma unroll
    for (int mi = 0; mi < 2; mi++) {
        #pragma unroll
        for (int half = 0; half < 2; half++) {
            int m = bm * 64 + wm * 32 + mi * 16 + gid + half * 8;
            float sam = g_sa[m];
            #pragma unroll
            for (int ni = 0; ni < 8; ni++) {
                int n = bn * 128 + wn * 64 + ni * 8 + tg * 2;
                float v0 = sam * g_swo[n]
                         * (16384.f * (float)acc1[mi][ni][half * 2 + 0]
                          + 128.f   * (float)acc2[mi][ni][half * 2 + 0]);
                float v1 = sam * g_swo[n + 1]
                         * (16384.f * (float)acc1[mi][ni][half * 2 + 1]
                          + 128.f   * (float)acc2[mi][ni][half * 2 + 1]);
                float2 w; w.x = v0 + bo[n]; w.y = v1 + bo[n + 1];
                *(float2*)(out + (size_t)m * DD + n) = w;
            }
        }
    }
}

// ---------------------------------------------------------------------------
// Tensor-core flash attention (round-7/13/14 verbatim)
// ---------------------------------------------------------------------------
#define AT_SMEM (32768 + 2*32768)

__global__ __launch_bounds__(256) void attn_kernel()
{
    extern __shared__ char smem[];
    const uint32_t sb = smem_u32(smem);
    const int tid  = threadIdx.x;
    const int lane = tid & 31;
    const int w    = tid >> 5;

    const int qt = blockIdx.x, h = blockIdx.y, b = blockIdx.z;
    const size_t bh = (size_t)b * HH + h;

    const char* qh_g = (const char*)(g_qhi + (bh * SS + qt * 128) * EE);
    const char* ql_g = (const char*)(g_qlo + (bh * SS + qt * 128) * EE);
    const char* kh_g = (const char*)(g_khi + bh * SS * EE);
    const char* kl_g = (const char*)(g_klo + bh * SS * EE);
    const char* vh_g = (const char*)(g_vhi + bh * SS * EE);
    const char* vl_g = (const char*)(g_vlo + bh * SS * EE);

    #pragma unroll
    for (int i = 0; i < 4; i++) {
        int idx = i * 256 + tid;
        int r = idx >> 3, c = idx & 7;
        cp16(sb + SW128(r * 128 + c * 16), qh_g + (size_t)r * 128 + c * 16);
        cp16(sb + 16384 + SW128(r * 128 + c * 16), ql_g + (size_t)r * 128 + c * 16);
    }

    auto load_kv = [&](int t, int s) {
        uint32_t kb = sb + 32768 + s * 32768;
        size_t rowbase = (size_t)t * 64 * 128;
        #pragma unroll
        for (int i = 0; i < 8; i++) {
            int tile = i >> 1;
            int r = (i & 1) * 32 + (tid >> 3);
            int c = tid & 7;
            const char* src = (tile == 0) ? kh_g : (tile == 1) ? kl_g
                            : (tile == 2) ? vh_g : vl_g;
            cp16(kb + tile * 8192 + SW128(r * 128 + c * 16),
                 src + rowbase + (size_t)r * 128 + c * 16);
        }
    };

    load_kv(0, 0);
    cp_commit();

    float oacc[8][4];
    #pragma unroll
    for (int ni = 0; ni < 8; ni++)
        #pragma unroll
        for (int j = 0; j < 4; j++) oacc[ni][j] = 0.f;
    float m0 = -1e30f, m1 = -1e30f, l0 = 0.f, l1 = 0.f;

    uint32_t qh[4][4], ql[4][4];

    const int krow = (lane & 7) + ((lane >> 3) & 1) * 8;
    const int kch  = (lane >> 4) * 16;

    for (int t = 0; t < 8; t++) {
        cp_wait<0>();
        __syncthreads();

        if (t == 0) {
            #pragma unroll
            for (int ks = 0; ks < 4; ks++) {
                uint32_t ad = SW128((w * 16 + (lane & 15)) * 128 + ks * 32 + (lane >> 4) * 16);
                ldsm4(qh[ks][0], qh[ks][1], qh[ks][2], qh[ks][3], sb + ad);
                ldsm4(ql[ks][0], ql[ks][1], ql[ks][2], ql[ks][3], sb + 16384 + ad);
            }
        }

        if (t < 7) { load_kv(t + 1, (t + 1) & 1); cp_commit(); }
        else       { cp_commit(); }

        uint32_t kb = sb + 32768 + (t & 1) * 32768;

        float sacc[8][4];
        #pragma unroll
        for (int ni = 0; ni < 8; ni++)
            #pragma unroll
            for (int j = 0; j < 4; j++) sacc[ni][j] = 0.f;

        #pragma unroll
        for (int ks = 0; ks < 4; ks++) {
            #pragma unroll
            for (int nj = 0; nj < 4; nj++) {
                uint32_t ad = SW128((nj * 16 + krow) * 128 + ks * 32 + kch);
                uint32_t h0, h1, h2, h3, e0, e1, e2, e3;
                ldsm4(h0, h1, h2, h3, kb + ad);
                ldsm4(e0, e1, e2, e3, kb + 8192 + ad);
                mma16816(sacc[2*nj][0], sacc[2*nj][1], sacc[2*nj][2], sacc[2*nj][3],
                         qh[ks][0], qh[ks][1], qh[ks][2], qh[ks][3], h0, h2);
                mma16816(sacc[2*nj+1][0], sacc[2*nj+1][1], sacc[2*nj+1][2], sacc[2*nj+1][3],
                         qh[ks][0], qh[ks][1], qh[ks][2], qh[ks][3], h1, h3);
                mma16816(sacc[2*nj][0], sacc[2*nj][1], sacc[2*nj][2], sacc[2*nj][3],
                         qh[ks][0], qh[ks][1], qh[ks][2], qh[ks][3], e0, e2);
                mma16816(sacc[2*nj+1][0], sacc[2*nj+1][1], sacc[2*nj+1][2], sacc[2*nj+1][3],
                         qh[ks][0], qh[ks][1], qh[ks][2], qh[ks][3], e1, e3);
                mma16816(sacc[2*nj][0], sacc[2*nj][1], sacc[2*nj][2], sacc[2*nj][3],
                         ql[ks][0], ql[ks][1], ql[ks][2], ql[ks][3], h0, h2);
                mma16816(sacc[2*nj+1][0], sacc[2*nj+1][1], sacc[2*nj+1][2], sacc[2*nj+1][3],
                         ql[ks][0], ql[ks][1], ql[ks][2], ql[ks][3], h1, h3);
            }
        }

        float ml0 = -1e30f, ml1 = -1e30f;
        #pragma unroll
        for (int ni = 0; ni < 8; ni++) {
            sacc[ni][0] *= 0.125f; sacc[ni][1] *= 0.125f;
            sacc[ni][2] *= 0.125f; sacc[ni][3] *= 0.125f;
            ml0 = fmaxf(ml0, fmaxf(sacc[ni][0], sacc[ni][1]));
            ml1 = fmaxf(ml1, fmaxf(sacc[ni][2], sacc[ni][3]));
        }
        ml0 = fmaxf(ml0, __shfl_xor_sync(0xffffffffu, ml0, 1));
        ml0 = fmaxf(ml0, __shfl_xor_sync(0xffffffffu, ml0, 2));
        ml1 = fmaxf(ml1, __shfl_xor_sync(0xffffffffu, ml1, 1));
        ml1 = fmaxf(ml1, __shfl_xor_sync(0xffffffffu, ml1, 2));

        float mn0 = fmaxf(m0, ml0), mn1 = fmaxf(m1, ml1);
        float corr0 = __expf(m0 - mn0), corr1 = __expf(m1 - mn1);
        m0 = mn0; m1 = mn1;

        float rs0 = 0.f, rs1 = 0.f;
        #pragma unroll
        for (int ni = 0; ni < 8; ni++) {
            sacc[ni][0] = __expf(sacc[ni][0] - mn0);
            sacc[ni][1] = __expf(sacc[ni][1] - mn0);
            sacc[ni][2] = __expf(sacc[ni][2] - mn1);
            sacc[ni][3] = __expf(sacc[ni][3] - mn1);
            rs0 += sacc[ni][0] + sacc[ni][1];
            rs1 += sacc[ni][2] + sacc[ni][3];
        }
        rs0 += __shfl_xor_sync(0xffffffffu, rs0, 1);
        rs0 += __shfl_xor_sync(0xffffffffu, rs0, 2);
        rs1 += __shfl_xor_sync(0xffffffffu, rs1, 1);
        rs1 += __shfl_xor_sync(0xffffffffu, rs1, 2);
        l0 = l0 * corr0 + rs0;
        l1 = l1 * corr1 + rs1;
        #pragma unroll
        for (int ni = 0; ni < 8; ni++) {
            oacc[ni][0] *= corr0; oacc[ni][1] *= corr0;
            oacc[ni][2] *= corr1; oacc[ni][3] *= corr1;
        }

        #pragma unroll
        for (int ks = 0; ks < 4; ks++) {
            float* p0 = sacc[2 * ks];
            float* p1 = sacc[2 * ks + 1];
            uint32_t ah0 = pack_hi(p0[0], p0[1]);
            uint32_t ah1 = pack_hi(p0[2], p0[3]);
            uint32_t ah2 = pack_hi(p1[0], p1[1]);
            uint32_t ah3 = pack_hi(p1[2], p1[3]);
            uint32_t al0 = pack_rn(p0[0] - trunc_bf(p0[0]), p0[1] - trunc_bf(p0[1]));
            uint32_t al1 = pack_rn(p0[2] - trunc_bf(p0[2]), p0[3] - trunc_bf(p0[3]));
            uint32_t al2 = pack_rn(p1[0] - trunc_bf(p1[0]), p1[1] - trunc_bf(p1[1]));
            uint32_t al3 = pack_rn(p1[2] - trunc_bf(p1[2]), p1[3] - trunc_bf(p1[3]));
            #pragma unroll
            for (int ep = 0; ep < 4; ep++) {
                uint32_t ad = SW128((ks * 16 + krow) * 128 + ep * 32 + kch);
                uint32_t vh0, vh1, vh2, vh3, vl0_, vl1_, vl2_, vl3_;
                ldsm4t(vh0, vh1, vh2, vh3, kb + 16384 + ad);
                ldsm4t(vl0_, vl1_, vl2_, vl3_, kb + 24576 + ad);
                mma16816(oacc[2*ep][0], oacc[2*ep][1], oacc[2*ep][2], oacc[2*ep][3],
                         ah0, ah1, ah2, ah3, vh0, vh1);
                mma16816(oacc[2*ep+1][0], oacc[2*ep+1][1], oacc[2*ep+1][2], oacc[2*ep+1][3],
                         ah0, ah1, ah2, ah3, vh2, vh3);
                mma16816(oacc[2*ep][0], oacc[2*ep][1], oacc[2*ep][2], oacc[2*ep][3],
                         ah0, ah1, ah2, ah3, vl0_, vl1_);
                mma16816(oacc[2*ep+1][0], oacc[2*ep+1][1], oacc[2*ep+1][2], oacc[2*ep+1][3],
                         ah0, ah1, ah2, ah3, vl2_, vl3_);
                mma16816(oacc[2*ep][0], oacc[2*ep][1], oacc[2*ep][2], oacc[2*ep][3],
                         al0, al1, al2, al3, vh0, vh1);
                mma16816(oacc[2*ep+1][0], oacc[2*ep+1][1], oacc[2*ep+1][2], oacc[2*ep+1][3],
                         al0, al1, al2, al3, vh2, vh3);
            }
        }
    }

    float inv0 = 1.f / l0, inv1 = 1.f / l1;
    int mrow = b * SS + qt * 128 + w * 16 + (lane >> 2);
    int colb = h * 64 + (lane & 3) * 2;
    #pragma unroll
    for (int ni = 0; ni < 8; ni++) {
        float v0 = oacc[ni][0] * inv0, v1 = oacc[ni][1] * inv0;
        float v2 = oacc[ni][2] * inv1, v3 = oacc[ni][3] * inv1;
        size_t base0 = (size_t)mrow * DD + colb + ni * 8;
        size_t base1 = (size_t)(mrow + 8) * DD + colb + ni * 8;
        *(uint32_t*)(g_ashi + base0) = pack_hi(v0, v1);
        *(uint32_t*)(g_aslo + base0) = pack_rn(v0 - trunc_bf(v0), v1 - trunc_bf(v1));
        *(uint32_t*)(g_ashi + base1) = pack_hi(v2, v3);
        *(uint32_t*)(g_aslo + base1) = pack_rn(v2 - trunc_bf(v2), v3 - trunc_bf(v3));
    }
}

// ---------------------------------------------------------------------------
extern "C" void kernel_launch(void* const* d_in, const int* in_sizes, int n_in,
                              void* d_out, int out_size)
{
    const float* x  = (const float*)d_in[0];
    const float* Wq = (const float*)d_in[1];
    const float* Wk = (const float*)d_in[2];
    const float* Wv = (const float*)d_in[3];
    const float* bq = (const float*)d_in[4];
    const float* bk = (const float*)d_in[5];
    const float* bv = (const float*)d_in[6];
    const float* Wo = (const float*)d_in[7];
    const float* bo = (const float*)d_in[8];
    float* out = (float*)d_out;

    cudaFuncSetAttribute(gemm_qkv_i8, cudaFuncAttributeMaxDynamicSharedMemorySize, I_SMEM);
    cudaFuncSetAttribute(gemm_proj_i8, cudaFuncAttributeMaxDynamicSharedMemorySize, I_SMEM);
    cudaFuncSetAttribute(attn_kernel, cudaFuncAttributeMaxDynamicSharedMemorySize, AT_SMEM);

    quant_x<<<M_TOT, 256>>>(x);
    quant_wqkv<<<N_QKV, 256>>>(Wq, Wk, Wv);
    quant_wo<<<DD, 256>>>(Wo);

    gemm_qkv_i8<<<dim3(N_QKV / 128, M_TOT / 64), 128, I_SMEM>>>(bq, bk, bv);

    attn_kernel<<<dim3(SS / 128, HH, BB), 256, AT_SMEM>>>();

    quant_att<<<M_TOT, 256>>>();

    gemm_proj_i8<<<dim3(DD / 128, M_TOT / 64), 128, I_SMEM>>>(bo, out);
}

// round 16
// speedup vs baseline: 1.4681x; 1.0419x over previous
#include <cuda_runtime.h>
#include <cuda_bf16.h>
#include <math.h>
#include <stdint.h>

#define BB 32
#define SS 512
#define DD 768
#define HH 12
#define EE 64

#define M_TOT (BB*SS)        // 16384
#define N_QKV (3*DD)         // 2304
#define NKCI  (DD/128)       // 6 k-chunks of 128 (int8 GEMMs)

// int8 GEMM smem per stage (CTA tile 64x128):
// A1 8K | A2 8K | B1 16K | B2 16K = 48KB, 2 stages
#define I_A1 0
#define I_A2 8192
#define I_B1 16384
#define I_B2 32768
#define ISTG 49152
#define I_SMEM (2*ISTG)      // 96KB

// ---------------- device scratch ----------------
__device__ int8_t g_x1[M_TOT*DD], g_x2[M_TOT*DD];      // x quant
__device__ float  g_sx[M_TOT];
__device__ int8_t g_w1[N_QKV*DD], g_w2[N_QKV*DD];      // qkv W^T quant
__device__ float  g_sw[N_QKV];
__device__ int8_t g_wo1[DD*DD],   g_wo2[DD*DD];        // Wo^T quant
__device__ float  g_swo[DD];
__device__ int8_t g_a1[M_TOT*DD], g_a2[M_TOT*DD];      // attn out quant
__device__ float  g_sa[M_TOT];
__device__ __nv_bfloat16 g_ashi[M_TOT*DD], g_aslo[M_TOT*DD];   // attn out split
// q/k int8 split + per-row scales; v bf16 split
__device__ int8_t g_q1[BB*HH*SS*EE], g_q2[BB*HH*SS*EE];
__device__ float  g_sq_[BB*HH*SS];
__device__ int8_t g_k1[BB*HH*SS*EE], g_k2[BB*HH*SS*EE];
__device__ float  g_sk_[BB*HH*SS];
__device__ __nv_bfloat16 g_vhi[BB*HH*SS*EE], g_vlo[BB*HH*SS*EE];

// ---------------- helpers ----------------
#define SW128(o) ((o) ^ (((o) >> 3) & 0x70))
#define SW64(o)  ((o) ^ (((o) >> 3) & 0x30))

__device__ __forceinline__ uint32_t smem_u32(const void* p) {
    return (uint32_t)__cvta_generic_to_shared(p);
}
__device__ __forceinline__ void cp16(uint32_t dst, const void* src) {
    asm volatile("cp.async.cg.shared.global [%0], [%1], 16;" :: "r"(dst), "l"(src) : "memory");
}
__device__ __forceinline__ void cp_commit() {
    asm volatile("cp.async.commit_group;" ::: "memory");
}
template <int N> __device__ __forceinline__ void cp_wait() {
    asm volatile("cp.async.wait_group %0;" :: "n"(N) : "memory");
}
__device__ __forceinline__ void ldsm4(uint32_t& a, uint32_t& b, uint32_t& c, uint32_t& d,
                                      uint32_t addr) {
    asm volatile("ldmatrix.sync.aligned.m8n8.x4.shared.b16 {%0,%1,%2,%3}, [%4];"
                 : "=r"(a), "=r"(b), "=r"(c), "=r"(d) : "r"(addr));
}
__device__ __forceinline__ void ldsm4t(uint32_t& a, uint32_t& b, uint32_t& c, uint32_t& d,
                                       uint32_t addr) {
    asm volatile("ldmatrix.sync.aligned.m8n8.x4.trans.shared.b16 {%0,%1,%2,%3}, [%4];"
                 : "=r"(a), "=r"(b), "=r"(c), "=r"(d) : "r"(addr));
}
__device__ __forceinline__ void mma16816(float& c0, float& c1, float& c2, float& c3,
                                         uint32_t a0, uint32_t a1, uint32_t a2, uint32_t a3,
                                         uint32_t b0, uint32_t b1) {
    asm volatile(
        "mma.sync.aligned.m16n8k16.row.col.f32.bf16.bf16.f32 "
        "{%0,%1,%2,%3}, {%4,%5,%6,%7}, {%8,%9}, {%0,%1,%2,%3};"
        : "+f"(c0), "+f"(c1), "+f"(c2), "+f"(c3)
        : "r"(a0), "r"(a1), "r"(a2), "r"(a3), "r"(b0), "r"(b1));
}
__device__ __forceinline__ void imma16832(int& c0, int& c1, int& c2, int& c3,
                                          uint32_t a0, uint32_t a1, uint32_t a2, uint32_t a3,
                                          uint32_t b0, uint32_t b1) {
    asm volatile(
        "mma.sync.aligned.m16n8k32.row.col.s32.s8.s8.s32 "
        "{%0,%1,%2,%3}, {%4,%5,%6,%7}, {%8,%9}, {%0,%1,%2,%3};"
        : "+r"(c0), "+r"(c1), "+r"(c2), "+r"(c3)
        : "r"(a0), "r"(a1), "r"(a2), "r"(a3), "r"(b0), "r"(b1));
}
__device__ __forceinline__ uint32_t pack_hi(float v0, float v1) {
    return __byte_perm(__float_as_uint(v0), __float_as_uint(v1), 0x7632);
}
__device__ __forceinline__ float trunc_bf(float v) {
    return __uint_as_float(__float_as_uint(v) & 0xffff0000u);
}
__device__ __forceinline__ uint32_t pack_rn(float l0, float l1) {
    uint32_t r;
    asm("cvt.rn.bf16x2.f32 %0, %1, %2;" : "=r"(r) : "f"(l1), "f"(l0));
    return r;
}

// ---------------------------------------------------------------------------
// single-pass quant kernels (round-15 verbatim)
// ---------------------------------------------------------------------------
#define QSPLIT(V, INV, OUT1, OUT2, IDX) do { \
        float ai_ = rintf((V) * (INV)); \
        int a1_ = (int)rintf(ai_ * 0.0078125f); \
        int a2_ = (int)ai_ - 128 * a1_; \
        OUT1[IDX] = (int8_t)a1_; \
        OUT2[IDX] = (int8_t)a2_; \
    } while (0)

__global__ __launch_bounds__(256) void quant_x(const float* __restrict__ x) {
    int row = blockIdx.x;
    int t = threadIdx.x;
    __shared__ float red[256];
    float v0 = x[(size_t)row * DD + t];
    float v1 = x[(size_t)row * DD + t + 256];
    float v2 = x[(size_t)row * DD + t + 512];
    float m = fmaxf(fabsf(v0), fmaxf(fabsf(v1), fabsf(v2)));
    red[t] = m;
    __syncthreads();
    for (int s = 128; s > 0; s >>= 1) {
        if (t < s) red[t] = fmaxf(red[t], red[t + s]);
        __syncthreads();
    }
    float mx = red[0];
    float inv = mx > 0.f ? 16256.f / mx : 0.f;
    if (t == 0) g_sx[row] = mx > 0.f ? mx / 16256.f : 0.f;
    QSPLIT(v0, inv, g_x1, g_x2, (size_t)row * DD + t);
    QSPLIT(v1, inv, g_x1, g_x2, (size_t)row * DD + t + 256);
    QSPLIT(v2, inv, g_x1, g_x2, (size_t)row * DD + t + 512);
}

__global__ __launch_bounds__(256) void quant_wqkv(
    const float* __restrict__ Wq, const float* __restrict__ Wk,
    const float* __restrict__ Wv)
{
    int row = blockIdx.x;
    int t = threadIdx.x;
    int which = row / DD;
    int rem = row - which * DD;
    int h = rem >> 6, e = rem & 63;
    const float* W = ((which == 0) ? Wq : (which == 1) ? Wk : Wv)
                   + (size_t)h * DD * EE + e;
    __shared__ float red[256];
    float v0 = W[(size_t)t * EE];
    float v1 = W[(size_t)(t + 256) * EE];
    float v2 = W[(size_t)(t + 512) * EE];
    float m = fmaxf(fabsf(v0), fmaxf(fabsf(v1), fabsf(v2)));
    red[t] = m;
    __syncthreads();
    for (int s = 128; s > 0; s >>= 1) {
        if (t < s) red[t] = fmaxf(red[t], red[t + s]);
        __syncthreads();
    }
    float mx = red[0];
    float inv = mx > 0.f ? 16256.f / mx : 0.f;
    if (t == 0) g_sw[row] = mx > 0.f ? mx / 16256.f : 0.f;
    QSPLIT(v0, inv, g_w1, g_w2, (size_t)row * DD + t);
    QSPLIT(v1, inv, g_w1, g_w2, (size_t)row * DD + t + 256);
    QSPLIT(v2, inv, g_w1, g_w2, (size_t)row * DD + t + 512);
}

__global__ __launch_bounds__(256) void quant_att() {
    int row = blockIdx.x;
    int t = threadIdx.x;
    __shared__ float red[256];
    float v0 = __bfloat162float(g_ashi[(size_t)row * DD + t])
             + __bfloat162float(g_aslo[(size_t)row * DD + t]);
    float v1 = __bfloat162float(g_ashi[(size_t)row * DD + t + 256])
             + __bfloat162float(g_aslo[(size_t)row * DD + t + 256]);
    float v2 = __bfloat162float(g_ashi[(size_t)row * DD + t + 512])
             + __bfloat162float(g_aslo[(size_t)row * DD + t + 512]);
    float m = fmaxf(fabsf(v0), fmaxf(fabsf(v1), fabsf(v2)));
    red[t] = m;
    __syncthreads();
    for (int s = 128; s > 0; s >>= 1) {
        if (t < s) red[t] = fmaxf(red[t], red[t + s]);
        __syncthreads();
    }
    float mx = red[0];
    float inv = mx > 0.f ? 16256.f / mx : 0.f;
    if (t == 0) g_sa[row] = mx > 0.f ? mx / 16256.f : 0.f;
    QSPLIT(v0, inv, g_a1, g_a2, (size_t)row * DD + t);
    QSPLIT(v1, inv, g_a1, g_a2, (size_t)row * DD + t + 256);
    QSPLIT(v2, inv, g_a1, g_a2, (size_t)row * DD + t + 512);
}

__global__ __launch_bounds__(256) void quant_wo(const float* __restrict__ Wo) {
    int row = blockIdx.x;
    int t = threadIdx.x;
    __shared__ float red[256];
    float v0 = Wo[(size_t)t * DD + row];
    float v1 = Wo[(size_t)(t + 256) * DD + row];
    float v2 = Wo[(size_t)(t + 512) * DD + row];
    float m = fmaxf(fabsf(v0), fmaxf(fabsf(v1), fabsf(v2)));
    red[t] = m;
    __syncthreads();
    for (int s = 128; s > 0; s >>= 1) {
        if (t < s) red[t] = fmaxf(red[t], red[t + s]);
        __syncthreads();
    }
    float mx = red[0];
    float inv = mx > 0.f ? 16256.f / mx : 0.f;
    if (t == 0) g_swo[row] = mx > 0.f ? mx / 16256.f : 0.f;
    QSPLIT(v0, inv, g_wo1, g_wo2, (size_t)row * DD + t);
    QSPLIT(v1, inv, g_wo1, g_wo2, (size_t)row * DD + t + 256);
    QSPLIT(v2, inv, g_wo1, g_wo2, (size_t)row * DD + t + 512);
}

// ---------------------------------------------------------------------------
// int8 qkv GEMM (CTA 64x128, 128 thr, warp 32x64, 2-stage).
// epilogue: q,k -> int8 split + per-row scale; v -> bf16 split.
// ---------------------------------------------------------------------------
__global__ __launch_bounds__(128) void gemm_qkv_i8(
    const float* __restrict__ b0, const float* __restrict__ b1,
    const float* __restrict__ b2)
{
    extern __shared__ char smem[];
    const uint32_t sbase = smem_u32(smem);
    const int tid  = threadIdx.x;
    const int lane = tid & 31;
    const int warp = tid >> 5;
    const int wm = warp >> 1;
    const int wn = warp & 1;

    const int bn = blockIdx.x, bm = blockIdx.y;

    const char* A1p = (const char*)(g_x1 + (size_t)bm * 64 * DD);
    const char* A2p = (const char*)(g_x2 + (size_t)bm * 64 * DD);
    const char* B1p = (const char*)(g_w1 + (size_t)bn * 128 * DD);
    const char* B2p = (const char*)(g_w2 + (size_t)bn * 128 * DD);

    auto load_stage = [&](int kt, int s) {
        uint32_t sb = sbase + s * ISTG;
        size_t kb = (size_t)kt * 128;
        #pragma unroll
        for (int i = 0; i < 4; i++) {
            int idx = i * 128 + tid;
            int r = idx >> 3, c = idx & 7;
            uint32_t off = SW128(r * 128 + c * 16);
            size_t go = (size_t)r * DD + kb + c * 16;
            cp16(sb + I_A1 + off, A1p + go);
            cp16(sb + I_A2 + off, A2p + go);
        }
        #pragma unroll
        for (int i = 0; i < 8; i++) {
            int idx = i * 128 + tid;
            int r = idx >> 3, c = idx & 7;
            uint32_t off = SW128(r * 128 + c * 16);
            size_t go = (size_t)r * DD + kb + c * 16;
            cp16(sb + I_B1 + off, B1p + go);
            cp16(sb + I_B2 + off, B2p + go);
        }
        cp_commit();
    };

    int acc1[2][8][4], acc2[2][8][4];
    #pragma unroll
    for (int mi = 0; mi < 2; mi++)
        #pragma unroll
        for (int ni = 0; ni < 8; ni++)
            #pragma unroll
            for (int j = 0; j < 4; j++) { acc1[mi][ni][j] = 0; acc2[mi][ni][j] = 0; }

    load_stage(0, 0);

    const int a_row = wm * 32 + (lane & 15);
    const int a_chb = (lane >> 4) * 16;
    const int b_row = wn * 64 + (lane & 7) + ((lane >> 3) & 1) * 8;
    const int b_chb = (lane >> 4) * 16;

    for (int kt = 0; kt < NKCI; kt++) {
        if (kt + 1 < NKCI) {
            load_stage(kt + 1, (kt + 1) & 1);
            cp_wait<1>();
        } else {
            cp_wait<0>();
        }
        __syncthreads();

        uint32_t sb = sbase + (kt & 1) * ISTG;

        #pragma unroll
        for (int ks = 0; ks < 4; ks++) {
            uint32_t a1f[2][4], a2f[2][4], b1f[8][2], b2f[8][2];
            #pragma unroll
            for (int mi = 0; mi < 2; mi++)
                ldsm4(a1f[mi][0], a1f[mi][1], a1f[mi][2], a1f[mi][3],
                      sb + I_A1 + SW128((a_row + mi * 16) * 128 + ks * 32 + a_chb));
            #pragma unroll
            for (int p = 0; p < 4; p++) {
                uint32_t r0, r1, r2, r3;
                ldsm4(r0, r1, r2, r3,
                      sb + I_B1 + SW128((b_row + p * 16) * 128 + ks * 32 + b_chb));
                b1f[2*p][0] = r0; b1f[2*p][1] = r2;
                b1f[2*p+1][0] = r1; b1f[2*p+1][1] = r3;
            }
            #pragma unroll
            for (int mi = 0; mi < 2; mi++)
                #pragma unroll
                for (int ni = 0; ni < 8; ni++)
                    imma16832(acc1[mi][ni][0], acc1[mi][ni][1], acc1[mi][ni][2], acc1[mi][ni][3],
                              a1f[mi][0], a1f[mi][1], a1f[mi][2], a1f[mi][3],
                              b1f[ni][0], b1f[ni][1]);
            #pragma unroll
            for (int p = 0; p < 4; p++) {
                uint32_t r0, r1, r2, r3;
                ldsm4(r0, r1, r2, r3,
                      sb + I_B2 + SW128((b_row + p * 16) * 128 + ks * 32 + b_chb));
                b2f[2*p][0] = r0; b2f[2*p][1] = r2;
                b2f[2*p+1][0] = r1; b2f[2*p+1][1] = r3;
            }
            #pragma unroll
            for (int mi = 0; mi < 2; mi++)
                #pragma unroll
                for (int ni = 0; ni < 8; ni++)
                    imma16832(acc2[mi][ni][0], acc2[mi][ni][1], acc2[mi][ni][2], acc2[mi][ni][3],
                              a1f[mi][0], a1f[mi][1], a1f[mi][2], a1f[mi][3],
                              b2f[ni][0], b2f[ni][1]);
            #pragma unroll
            for (int mi = 0; mi < 2; mi++)
                ldsm4(a2f[mi][0], a2f[mi][1], a2f[mi][2], a2f[mi][3],
                      sb + I_A2 + SW128((a_row + mi * 16) * 128 + ks * 32 + a_chb));
            #pragma unroll
            for (int mi = 0; mi < 2; mi++)
                #pragma unroll
                for (int ni = 0; ni < 8; ni++)
                    imma16832(acc2[mi][ni][0], acc2[mi][ni][1], acc2[mi][ni][2], acc2[mi][ni][3],
                              a2f[mi][0], a2f[mi][1], a2f[mi][2], a2f[mi][3],
                              b1f[ni][0], b1f[ni][1]);
        }
        __syncthreads();
    }

    // epilogue
    const int gid = lane >> 2;
    const int tg  = lane & 3;
    const int which = (bn * 128) / DD;             // uniform per CTA
    const int rem0 = bn * 128 + wn * 64 - which * DD;
    const int h = rem0 >> 6;                       // head (warp covers full 64-e row)
    const int nbase = bn * 128 + wn * 64;

    if (which == 2) {
        // V path: bf16 split (unchanged)
        #pragma unroll
        for (int mi = 0; mi < 2; mi++) {
            #pragma unroll
            for (int half = 0; half < 2; half++) {
                int m = bm * 64 + wm * 32 + mi * 16 + gid + half * 8;
                float sam = g_sx[m];
                #pragma unroll
                for (int ni = 0; ni < 8; ni++) {
                    int n = nbase + ni * 8 + tg * 2;
                    int e = ni * 8 + tg * 2;
                    float v0 = sam * g_sw[n]
                             * (16384.f * (float)acc1[mi][ni][half * 2 + 0]
                              + 128.f   * (float)acc2[mi][ni][half * 2 + 0])
                             + b2[h * EE + e];
                    float v1 = sam * g_sw[n + 1]
                             * (16384.f * (float)acc1[mi][ni][half * 2 + 1]
                              + 128.f   * (float)acc2[mi][ni][half * 2 + 1])
                             + b2[h * EE + e + 1];
                    size_t off = (((size_t)(m >> 9) * HH + h) * SS + (m & 511)) * EE + e;
                    *(uint32_t*)(g_vhi + off) = pack_hi(v0, v1);
                    *(uint32_t*)(g_vlo + off) = pack_rn(v0 - trunc_bf(v0), v1 - trunc_bf(v1));
                }
            }
        }
    } else {
        // Q / K path: split-int8 + per-row scale
        const float* bp0 = (which == 0) ? b0 : b1;
        float* sqp = (which == 0) ? g_sq_ : g_sk_;
        int8_t* o1 = (which == 0) ? g_q1 : g_k1;
        int8_t* o2 = (which == 0) ? g_q2 : g_k2;
        #pragma unroll
        for (int mi = 0; mi < 2; mi++) {
            #pragma unroll
            for (int half = 0; half < 2; half++) {
                int m = bm * 64 + wm * 32 + mi * 16 + gid + half * 8;
                float sam = g_sx[m];
                float vv0[8], vv1[8];
                float mr = 0.f;
                #pragma unroll
                for (int ni = 0; ni < 8; ni++) {
                    int n = nbase + ni * 8 + tg * 2;
                    int e = ni * 8 + tg * 2;
                    float v0 = sam * g_sw[n]
                             * (16384.f * (float)acc1[mi][ni][half * 2 + 0]
                              + 128.f   * (float)acc2[mi][ni][half * 2 + 0])
                             + bp0[h * EE + e];
                    float v1 = sam * g_sw[n + 1]
                             * (16384.f * (float)acc1[mi][ni][half * 2 + 1]
                              + 128.f   * (float)acc2[mi][ni][half * 2 + 1])
                             + bp0[h * EE + e + 1];
                    vv0[ni] = v0; vv1[ni] = v1;
                    mr = fmaxf(mr, fmaxf(fabsf(v0), fabsf(v1)));
                }
                mr = fmaxf(mr, __shfl_xor_sync(0xffffffffu, mr, 1));
                mr = fmaxf(mr, __shfl_xor_sync(0xffffffffu, mr, 2));
                float inv = mr > 0.f ? 16256.f / mr : 0.f;
                size_t bhs = ((size_t)(m >> 9) * HH + h) * SS + (m & 511);
                if (tg == 0) sqp[bhs] = mr > 0.f ? mr / 16256.f : 0.f;
                #pragma unroll
                for (int ni = 0; ni < 8; ni++) {
                    int e = ni * 8 + tg * 2;
                    float a0 = rintf(vv0[ni] * inv);
                    int p1 = (int)rintf(a0 * 0.0078125f);
                    int p2 = (int)a0 - 128 * p1;
                    float a1r = rintf(vv1[ni] * inv);
                    int q1v = (int)rintf(a1r * 0.0078125f);
                    int q2v = (int)a1r - 128 * q1v;
                    char2 c1; c1.x = (char)p1; c1.y = (char)q1v;
                    char2 c2; c2.x = (char)p2; c2.y = (char)q2v;
                    *(char2*)(o1 + bhs * EE + e) = c1;
                    *(char2*)(o2 + bhs * EE + e) = c2;
                }
            }
        }
    }
}

// ---------------------------------------------------------------------------
// int8 proj GEMM (round-15 verbatim)
// ---------------------------------------------------------------------------
__global__ __launch_bounds__(128) void gemm_proj_i8(
    const float* __restrict__ bo, float* __restrict__ out)
{
    extern __shared__ char smem[];
    const uint32_t sbase = smem_u32(smem);
    const int tid  = threadIdx.x;
    const int lane = tid & 31;
    const int warp = tid >> 5;
    const int wm = warp >> 1;
    const int wn = warp & 1;

    const int bn = blockIdx.x, bm = blockIdx.y;

    const char* A1p = (const char*)(g_a1 + (size_t)bm * 64 * DD);
    const char* A2p = (const char*)(g_a2 + (size_t)bm * 64 * DD);
    const char* B1p = (const char*)(g_wo1 + (size_t)bn * 128 * DD);
    const char* B2p = (const char*)(g_wo2 + (size_t)bn * 128 * DD);

    auto load_stage = [&](int kt, int s) {
        uint32_t sb = sbase + s * ISTG;
        size_t kb = (size_t)kt * 128;
        #pragma unroll
        for (int i = 0; i < 4; i++) {
            int idx = i * 128 + tid;
            int r = idx >> 3, c = idx & 7;
            uint32_t off = SW128(r * 128 + c * 16);
            size_t go = (size_t)r * DD + kb + c * 16;
            cp16(sb + I_A1 + off, A1p + go);
            cp16(sb + I_A2 + off, A2p + go);
        }
        #pragma unroll
        for (int i = 0; i < 8; i++) {
            int idx = i * 128 + tid;
            int r = idx >> 3, c = idx & 7;
            uint32_t off = SW128(r * 128 + c * 16);
            size_t go = (size_t)r * DD + kb + c * 16;
            cp16(sb + I_B1 + off, B1p + go);
            cp16(sb + I_B2 + off, B2p + go);
        }
        cp_commit();
    };

    int acc1[2][8][4], acc2[2][8][4];
    #pragma unroll
    for (int mi = 0; mi < 2; mi++)
        #pragma unroll
        for (int ni = 0; ni < 8; ni++)
            #pragma unroll
            for (int j = 0; j < 4; j++) { acc1[mi][ni][j] = 0; acc2[mi][ni][j] = 0; }

    load_stage(0, 0);

    const int a_row = wm * 32 + (lane & 15);
    const int a_chb = (lane >> 4) * 16;
    const int b_row = wn * 64 + (lane & 7) + ((lane >> 3) & 1) * 8;
    const int b_chb = (lane >> 4) * 16;

    for (int kt = 0; kt < NKCI; kt++) {
        if (kt + 1 < NKCI) {
            load_stage(kt + 1, (kt + 1) & 1);
            cp_wait<1>();
        } else {
            cp_wait<0>();
        }
        __syncthreads();

        uint32_t sb = sbase + (kt & 1) * ISTG;

        #pragma unroll
        for (int ks = 0; ks < 4; ks++) {
            uint32_t a1f[2][4], a2f[2][4], b1f[8][2], b2f[8][2];
            #pragma unroll
            for (int mi = 0; mi < 2; mi++)
                ldsm4(a1f[mi][0], a1f[mi][1], a1f[mi][2], a1f[mi][3],
                      sb + I_A1 + SW128((a_row + mi * 16) * 128 + ks * 32 + a_chb));
            #pragma unroll
            for (int p = 0; p < 4; p++) {
                uint32_t r0, r1, r2, r3;
                ldsm4(r0, r1, r2, r3,
                      sb + I_B1 + SW128((b_row + p * 16) * 128 + ks * 32 + b_chb));
                b1f[2*p][0] = r0; b1f[2*p][1] = r2;
                b1f[2*p+1][0] = r1; b1f[2*p+1][1] = r3;
            }
            #pragma unroll
            for (int mi = 0; mi < 2; mi++)
                #pragma unroll
                for (int ni = 0; ni < 8; ni++)
                    imma16832(acc1[mi][ni][0], acc1[mi][ni][1], acc1[mi][ni][2], acc1[mi][ni][3],
                              a1f[mi][0], a1f[mi][1], a1f[mi][2], a1f[mi][3],
                              b1f[ni][0], b1f[ni][1]);
            #pragma unroll
            for (int p = 0; p < 4; p++) {
                uint32_t r0, r1, r2, r3;
                ldsm4(r0, r1, r2, r3,
                      sb + I_B2 + SW128((b_row + p * 16) * 128 + ks * 32 + b_chb));
                b2f[2*p][0] = r0; b2f[2*p][1] = r2;
                b2f[2*p+1][0] = r1; b2f[2*p+1][1] = r3;
            }
            #pragma unroll
            for (int mi = 0; mi < 2; mi++)
                #pragma unroll
                for (int ni = 0; ni < 8; ni++)
                    imma16832(acc2[mi][ni][0], acc2[mi][ni][1], acc2[mi][ni][2], acc2[mi][ni][3],
                              a1f[mi][0], a1f[mi][1], a1f[mi][2], a1f[mi][3],
                              b2f[ni][0], b2f[ni][1]);
            #pragma unroll
            for (int mi = 0; mi < 2; mi++)
                ldsm4(a2f[mi][0], a2f[mi][1], a2f[mi][2], a2f[mi][3],
                      sb + I_A2 + SW128((a_row + mi * 16) * 128 + ks * 32 + a_chb));
            #pragma unroll
            for (int mi = 0; mi < 2; mi++)
                #pragma unroll
                for (int ni = 0; ni < 8; ni++)
                    imma16832(acc2[mi][ni][0], acc2[mi][ni][1], acc2[mi][ni][2], acc2[mi][ni][3],
                              a2f[mi][0], a2f[mi][1], a2f[mi][2], a2f[mi][3],
                              b1f[ni][0], b1f[ni][1]);
        }
        __syncthreads();
    }

    const int gid = lane >> 2;
    const int tg  = lane & 3;
    #pragma unroll
    for (int mi = 0; mi < 2; mi++) {
        #pragma unroll
        for (int half = 0; half < 2; half++) {
            int m = bm * 64 + wm * 32 + mi * 16 + gid + half * 8;
            float sam = g_sa[m];
            #pragma unroll
            for (int ni = 0; ni < 8; ni++) {
                int n = bn * 128 + wn * 64 + ni * 8 + tg * 2;
                float v0 = sam * g_swo[n]
                         * (16384.f * (float)acc1[mi][ni][half * 2 + 0]
                          + 128.f   * (float)acc2[mi][ni][half * 2 + 0]);
                float v1 = sam * g_swo[n + 1]
                         * (16384.f * (float)acc1[mi][ni][half * 2 + 1]
                          + 128.f   * (float)acc2[mi][ni][half * 2 + 1]);
                float2 w; w.x = v0 + bo[n]; w.y = v1 + bo[n + 1];
                *(float2*)(out + (size_t)m * DD + n) = w;
            }
        }
    }
}

// ---------------------------------------------------------------------------
// Flash attention: int8 IMMA QK^T (exact s32 accum, dequant into softmax);
// bf16 split PV (unchanged). grid (S/128, H, B), 256 threads.
// smem: Q1 0..8K, Q2 8K..16K; stage s at 16K+s*STSZ:
//   K1+0(4K) K2+4K VH+8K(8K) VL+16K SK+24K(256B); STSZ=24832
// ---------------------------------------------------------------------------
#define ST_K1 0
#define ST_K2 4096
#define ST_VH 8192
#define ST_VL 16384
#define ST_SK 24576
#define STSZ  24832
#define AT_SMEM (16384 + 2*STSZ)

__global__ __launch_bounds__(256) void attn_kernel()
{
    extern __shared__ char smem[];
    const uint32_t sb = smem_u32(smem);
    const int tid  = threadIdx.x;
    const int lane = tid & 31;
    const int w    = tid >> 5;

    const int qt = blockIdx.x, h = blockIdx.y, b = blockIdx.z;
    const size_t bh = (size_t)b * HH + h;

    const char* q1_g = (const char*)(g_q1 + (bh * SS + qt * 128) * EE);
    const char* q2_g = (const char*)(g_q2 + (bh * SS + qt * 128) * EE);
    const char* k1_g = (const char*)(g_k1 + bh * SS * EE);
    const char* k2_g = (const char*)(g_k2 + bh * SS * EE);
    const char* vh_g = (const char*)(g_vhi + bh * SS * EE);
    const char* vl_g = (const char*)(g_vlo + bh * SS * EE);
    const char* sk_g = (const char*)(g_sk_ + bh * SS);

    // Q tiles: 128 rows x 64B each, sw64. 512 chunks per array.
    #pragma unroll
    for (int i = 0; i < 2; i++) {
        int idx = i * 256 + tid;
        int r = idx >> 2, c = idx & 3;
        cp16(sb + SW64(r * 64 + c * 16), q1_g + (size_t)r * 64 + c * 16);
        cp16(sb + 8192 + SW64(r * 64 + c * 16), q2_g + (size_t)r * 64 + c * 16);
    }

    auto load_kv = [&](int t, int s) {
        uint32_t kb = sb + 16384 + s * STSZ;
        size_t rb64  = (size_t)t * 64 * 64;
        size_t rb128 = (size_t)t * 64 * 128;
        {   // K1, K2: 64 rows x 4 chunks each = 256 chunks
            int r = tid >> 2, c = tid & 3;
            cp16(kb + ST_K1 + SW64(r * 64 + c * 16), k1_g + rb64 + (size_t)r * 64 + c * 16);
            cp16(kb + ST_K2 + SW64(r * 64 + c * 16), k2_g + rb64 + (size_t)r * 64 + c * 16);
        }
        #pragma unroll
        for (int i = 0; i < 2; i++) {     // VH, VL: 64 rows x 8 chunks
            int idx = i * 256 + tid;
            int r = idx >> 3, c = idx & 7;
            cp16(kb + ST_VH + SW128(r * 128 + c * 16), vh_g + rb128 + (size_t)r * 128 + c * 16);
            cp16(kb + ST_VL + SW128(r * 128 + c * 16), vl_g + rb128 + (size_t)r * 128 + c * 16);
        }
        if (tid < 16)                     // sk: 64 floats
            cp16(kb + ST_SK + tid * 16, sk_g + (size_t)t * 64 * 4 + tid * 16);
    };

    load_kv(0, 0);
    cp_commit();

    float oacc[8][4];
    #pragma unroll
    for (int ni = 0; ni < 8; ni++)
        #pragma unroll
        for (int j = 0; j < 4; j++) oacc[ni][j] = 0.f;
    float m0 = -1e30f, m1 = -1e30f, l0 = 0.f, l1 = 0.f;

    uint32_t q1f[2][4], q2f[2][4];

    const int krow = (lane & 7) + ((lane >> 3) & 1) * 8;
    const int kch  = (lane >> 4) * 16;
    const int gid  = lane >> 2;
    const int tg   = lane & 3;

    // per-thread q-row scales (rows fixed per thread for whole kernel)
    float sqv0 = g_sq_[bh * SS + qt * 128 + w * 16 + gid];
    float sqv1 = g_sq_[bh * SS + qt * 128 + w * 16 + gid + 8];
    const float sc0 = sqv0 * 0.125f, sc1 = sqv1 * 0.125f;

    for (int t = 0; t < 8; t++) {
        cp_wait<0>();
        __syncthreads();

        if (t == 0) {
            #pragma unroll
            for (int kc = 0; kc < 2; kc++) {
                uint32_t ad = SW64((w * 16 + (lane & 15)) * 64 + kc * 32 + (lane >> 4) * 16);
                ldsm4(q1f[kc][0], q1f[kc][1], q1f[kc][2], q1f[kc][3], sb + ad);
                ldsm4(q2f[kc][0], q2f[kc][1], q2f[kc][2], q2f[kc][3], sb + 8192 + ad);
            }
        }

        if (t < 7) { load_kv(t + 1, (t + 1) & 1); cp_commit(); }
        else       { cp_commit(); }

        uint32_t kb = sb + 16384 + (t & 1) * STSZ;
        const float* sks = (const float*)(smem + 16384 + (t & 1) * STSZ + ST_SK);

        // ---- S = Q.K^T via split-int8 IMMA (exact s32 accum) ----
        int s1a[8][4], s2a[8][4];
        #pragma unroll
        for (int ni = 0; ni < 8; ni++)
            #pragma unroll
            for (int j = 0; j < 4; j++) { s1a[ni][j] = 0; s2a[ni][j] = 0; }

        #pragma unroll
        for (int kc = 0; kc < 2; kc++) {
            #pragma unroll
            for (int nj = 0; nj < 4; nj++) {
                uint32_t ad = SW64((nj * 16 + krow) * 64 + kc * 32 + kch);
                uint32_t r0, r1, r2, r3, e0, e1, e2, e3;
                ldsm4(r0, r1, r2, r3, kb + ST_K1 + ad);
                ldsm4(e0, e1, e2, e3, kb + ST_K2 + ad);
                imma16832(s1a[2*nj][0], s1a[2*nj][1], s1a[2*nj][2], s1a[2*nj][3],
                          q1f[kc][0], q1f[kc][1], q1f[kc][2], q1f[kc][3], r0, r2);
                imma16832(s1a[2*nj+1][0], s1a[2*nj+1][1], s1a[2*nj+1][2], s1a[2*nj+1][3],
                          q1f[kc][0], q1f[kc][1], q1f[kc][2], q1f[kc][3], r1, r3);
                imma16832(s2a[2*nj][0], s2a[2*nj][1], s2a[2*nj][2], s2a[2*nj][3],
                          q1f[kc][0], q1f[kc][1], q1f[kc][2], q1f[kc][3], e0, e2);
                imma16832(s2a[2*nj+1][0], s2a[2*nj+1][1], s2a[2*nj+1][2], s2a[2*nj+1][3],
                          q1f[kc][0], q1f[kc][1], q1f[kc][2], q1f[kc][3], e1, e3);
                imma16832(s2a[2*nj][0], s2a[2*nj][1], s2a[2*nj][2], s2a[2*nj][3],
                          q2f[kc][0], q2f[kc][1], q2f[kc][2], q2f[kc][3], r0, r2);
                imma16832(s2a[2*nj+1][0], s2a[2*nj+1][1], s2a[2*nj+1][2], s2a[2*nj+1][3],
                          q2f[kc][0], q2f[kc][1], q2f[kc][2], q2f[kc][3], r1, r3);
            }
        }

        // dequant into fp32 logits (includes softmax 1/8 scale)
        float sacc[8][4];
        #pragma unroll
        for (int ni = 0; ni < 8; ni++) {
            float k0 = sks[ni * 8 + tg * 2];
            float k1s = sks[ni * 8 + tg * 2 + 1];
            sacc[ni][0] = sc0 * k0  * (16384.f * (float)s1a[ni][0] + 128.f * (float)s2a[ni][0]);
            sacc[ni][1] = sc0 * k1s * (16384.f * (float)s1a[ni][1] + 128.f * (float)s2a[ni][1]);
            sacc[ni][2] = sc1 * k0  * (16384.f * (float)s1a[ni][2] + 128.f * (float)s2a[ni][2]);
            sacc[ni][3] = sc1 * k1s * (16384.f * (float)s1a[ni][3] + 128.f * (float)s2a[ni][3]);
        }

        // ---- online softmax (warp-local rows) ----
        float ml0 = -1e30f, ml1 = -1e30f;
        #pragma unroll
        for (int ni = 0; ni < 8; ni++) {
            ml0 = fmaxf(ml0, fmaxf(sacc[ni][0], sacc[ni][1]));
            ml1 = fmaxf(ml1, fmaxf(sacc[ni][2], sacc[ni][3]));
        }
        ml0 = fmaxf(ml0, __shfl_xor_sync(0xffffffffu, ml0, 1));
        ml0 = fmaxf(ml0, __shfl_xor_sync(0xffffffffu, ml0, 2));
        ml1 = fmaxf(ml1, __shfl_xor_sync(0xffffffffu, ml1, 1));
        ml1 = fmaxf(ml1, __shfl_xor_sync(0xffffffffu, ml1, 2));

        float mn0 = fmaxf(m0, ml0), mn1 = fmaxf(m1, ml1);
        float corr0 = __expf(m0 - mn0), corr1 = __expf(m1 - mn1);
        m0 = mn0; m1 = mn1;

        float rs0 = 0.f, rs1 = 0.f;
        #pragma unroll
        for (int ni = 0; ni < 8; ni++) {
            sacc[ni][0] = __expf(sacc[ni][0] - mn0);
            sacc[ni][1] = __expf(sacc[ni][1] - mn0);
            sacc[ni][2] = __expf(sacc[ni][2] - mn1);
            sacc[ni][3] = __expf(sacc[ni][3] - mn1);
            rs0 += sacc[ni][0] + sacc[ni][1];
            rs1 += sacc[ni][2] + sacc[ni][3];
        }
        rs0 += __shfl_xor_sync(0xffffffffu, rs0, 1);
        rs0 += __shfl_xor_sync(0xffffffffu, rs0, 2);
        rs1 += __shfl_xor_sync(0xffffffffu, rs1, 1);
        rs1 += __shfl_xor_sync(0xffffffffu, rs1, 2);
        l0 = l0 * corr0 + rs0;
        l1 = l1 * corr1 + rs1;
        #pragma unroll
        for (int ni = 0; ni < 8; ni++) {
            oacc[ni][0] *= corr0; oacc[ni][1] *= corr0;
            oacc[ni][2] *= corr1; oacc[ni][3] *= corr1;
        }

        // ---- O += P'V' (3-term bf16, unchanged) ----
        #pragma unroll
        for (int ks = 0; ks < 4; ks++) {
            float* p0 = sacc[2 * ks];
            float* p1 = sacc[2 * ks + 1];
            uint32_t ah0 = pack_hi(p0[0], p0[1]);
            uint32_t ah1 = pack_hi(p0[2], p0[3]);
            uint32_t ah2 = pack_hi(p1[0], p1[1]);
            uint32_t ah3 = pack_hi(p1[2], p1[3]);
            uint32_t al0 = pack_rn(p0[0] - trunc_bf(p0[0]), p0[1] - trunc_bf(p0[1]));
            uint32_t al1 = pack_rn(p0[2] - trunc_bf(p0[2]), p0[3] - trunc_bf(p0[3]));
            uint32_t al2 = pack_rn(p1[0] - trunc_bf(p1[0]), p1[1] - trunc_bf(p1[1]));
            uint32_t al3 = pack_rn(p1[2] - trunc_bf(p1[2]), p1[3] - trunc_bf(p1[3]));
            #pragma unroll
            for (int ep = 0; ep < 4; ep++) {
                uint32_t ad = SW128((ks * 16 + krow) * 128 + ep * 32 + kch);
                uint32_t vh0, vh1, vh2, vh3, vl0_, vl1_, vl2_, vl3_;
                ldsm4t(vh0, vh1, vh2, vh3, kb + ST_VH + ad);
                ldsm4t(vl0_, vl1_, vl2_, vl3_, kb + ST_VL + ad);
                mma16816(oacc[2*ep][0], oacc[2*ep][1], oacc[2*ep][2], oacc[2*ep][3],
                         ah0, ah1, ah2, ah3, vh0, vh1);
                mma16816(oacc[2*ep+1][0], oacc[2*ep+1][1], oacc[2*ep+1][2], oacc[2*ep+1][3],
                         ah0, ah1, ah2, ah3, vh2, vh3);
                mma16816(oacc[2*ep][0], oacc[2*ep][1], oacc[2*ep][2], oacc[2*ep][3],
                         ah0, ah1, ah2, ah3, vl0_, vl1_);
                mma16816(oacc[2*ep+1][0], oacc[2*ep+1][1], oacc[2*ep+1][2], oacc[2*ep+1][3],
                         ah0, ah1, ah2, ah3, vl2_, vl3_);
                mma16816(oacc[2*ep][0], oacc[2*ep][1], oacc[2*ep][2], oacc[2*ep][3],
                         al0, al1, al2, al3, vh0, vh1);
                mma16816(oacc[2*ep+1][0], oacc[2*ep+1][1], oacc[2*ep+1][2], oacc[2*ep+1][3],
                         al0, al1, al2, al3, vh2, vh3);
            }
        }
    }

    // epilogue: normalize + write hi/lo rows (unchanged)
    float inv0 = 1.f / l0, inv1 = 1.f / l1;
    int mrow = b * SS + qt * 128 + w * 16 + gid;
    int colb = h * 64 + tg * 2;
    #pragma unroll
    for (int ni = 0; ni < 8; ni++) {
        float v0 = oacc[ni][0] * inv0, v1 = oacc[ni][1] * inv0;
        float v2 = oacc[ni][2] * inv1, v3 = oacc[ni][3] * inv1;
        size_t base0 = (size_t)mrow * DD + colb + ni * 8;
        size_t base1 = (size_t)(mrow + 8) * DD + colb + ni * 8;
        *(uint32_t*)(g_ashi + base0) = pack_hi(v0, v1);
        *(uint32_t*)(g_aslo + base0) = pack_rn(v0 - trunc_bf(v0), v1 - trunc_bf(v1));
        *(uint32_t*)(g_ashi + base1) = pack_hi(v2, v3);
        *(uint32_t*)(g_aslo + base1) = pack_rn(v2 - trunc_bf(v2), v3 - trunc_bf(v3));
    }
}

// ---------------------------------------------------------------------------
extern "C" void kernel_launch(void* const* d_in, const int* in_sizes, int n_in,
                              void* d_out, int out_size)
{
    const float* x  = (const float*)d_in[0];
    const float* Wq = (const float*)d_in[1];
    const float* Wk = (const float*)d_in[2];
    const float* Wv = (const float*)d_in[3];
    const float* bq = (const float*)d_in[4];
    const float* bk = (const float*)d_in[5];
    const float* bv = (const float*)d_in[6];
    const float* Wo = (const float*)d_in[7];
    const float* bo = (const float*)d_in[8];
    float* out = (float*)d_out;

    cudaFuncSetAttribute(gemm_qkv_i8, cudaFuncAttributeMaxDynamicSharedMemorySize, I_SMEM);
    cudaFuncSetAttribute(gemm_proj_i8, cudaFuncAttributeMaxDynamicSharedMemorySize, I_SMEM);
    cudaFuncSetAttribute(attn_kernel, cudaFuncAttributeMaxDynamicSharedMemorySize, AT_SMEM);

    quant_x<<<M_TOT, 256>>>(x);
    quant_wqkv<<<N_QKV, 256>>>(Wq, Wk, Wv);
    quant_wo<<<DD, 256>>>(Wo);

    gemm_qkv_i8<<<dim3(N_QKV / 128, M_TOT / 64), 128, I_SMEM>>>(bq, bk, bv);

    attn_kernel<<<dim3(SS / 128, HH, BB), 256, AT_SMEM>>>();

    quant_att<<<M_TOT, 256>>>();

    gemm_proj_i8<<<dim3(DD / 128, M_TOT / 64), 128, I_SMEM>>>(bo, out);
}